// round 2
// baseline (speedup 1.0000x reference)
#include <cuda_runtime.h>
#include <cuda_bf16.h>

#define BD 5376
#define CHB 0
#define PNB 128
#define DNB 256
#define ATT_SUM 384
#define ATT_SQ 385
#define PIF 3.14159265358979323846f

__device__ float g_BE[65536], g_BO[65536], g_BPe[65536], g_BPo[65536];
__device__ float g_ce[256], g_co[256], g_attcoef[512];
__device__ float g_Wfold[49152], g_biasL[96], g_Mpatch[8192], g_bias2[512];
__device__ float g_xt[BD*512], g_xs[BD*256], g_xd[BD*256];
__device__ float g_zsplit[BD*512], g_u[BD*256], g_v[BD*256], g_z1[BD*512];
__device__ float g_s1[BD*512], g_z2[BD*512], g_zcp[BD*512];
__device__ float g_zres[BD*96], g_h[BD*96];
__device__ float g_energy[BD], g_norme[BD], g_att[BD], g_att1[BD];
__device__ float g_thr[1], g_stats[512];

__device__ __forceinline__ float gelu_f(float x){
    return 0.5f*x*(1.0f+erff(x*0.70710678118654752440f));
}

// ---- DCT matrices (fp32 rounding chain matches reference) + attcoef ----
__global__ void k_mats(const float* __restrict__ adw){
    int bm = blockIdx.x, t = threadIdx.x;
    if(bm < 256){
        int m = bm, j = t;
        float am = PIF*(float)(2*m+1);
        float ce = cosf(am*(float)(2*j)*(1.0f/1024.0f));
        float co = cosf(am*(float)(2*j+1)*(1.0f/1024.0f));
        g_BE[m*256+j] = 2.0f*ce;
        g_BO[m*256+j] = 2.0f*co;
        float bpe = ce*((j==0)?0.5f:1.0f)*(1.0f/512.0f);
        float bpo = co*(1.0f/512.0f);
        g_BPe[j*256+m] = bpe;
        g_BPo[j*256+m] = bpo;
        __shared__ float r1[256], r2[256];
        r1[t]=bpe; r2[t]=bpo; __syncthreads();
        for(int o=128;o>0;o>>=1){ if(t<o){ r1[t]+=r1[t+o]; r2[t]+=r2[t+o]; } __syncthreads(); }
        if(t==0){ g_ce[m]=r1[0]; g_co[m]=r2[0]; }
    } else {
        float rL = sqrtf(512.0f);
        for(int m=t; m<512; m+=256){
            float am = PIF*(float)(2*m+1);
            float s = 0.f;
            for(int k=0;k<5;k++){
                float c = 2.0f*cosf(am*(float)k*(1.0f/1024.0f));
                float so = (k==0)? (0.5f/rL) : (0.5f*sqrtf(2.0f)/rL);
                s += adw[k]*so*c;
            }
            g_attcoef[m]=s;
        }
    }
}

// ---- weight folding ----
__global__ void k_fold1(const float* __restrict__ We, const float* __restrict__ Wl,
                        const float* __restrict__ bl){
    int id = blockIdx.x*256+threadIdx.x;
    if(id<96) g_biasL[id]=bl[id];
    if(id>=49152) return;
    int c=id/96, t=id%96, n=c>>4, p=c&15;
    float s=0.f;
    for(int j=0;j<256;j++) s += We[p*256+j]*Wl[(n*256+j)*96+t];
    g_Wfold[id]=s;
}

__global__ void k_fold2(const float* __restrict__ We, const float* __restrict__ be,
                        const float* __restrict__ Wl, const float* __restrict__ Wd,
                        const float* __restrict__ bdres, const float* __restrict__ wdc,
                        const float* __restrict__ bdc){
    int id = blockIdx.x*256+threadIdx.x;
    if(id<8192){
        int n=id/256, q=(id>>4)&15, i=id&15;
        float s=0.f;
        #pragma unroll
        for(int p=0;p<16;p++) s += We[i*256+q*16+p]*wdc[n*16+p];
        for(int j=0;j<256;j++) s += We[i*256+j]*Wd[j*16+q];
        g_Mpatch[id]=s;
    } else if(id<8704){
        int c=id-8192, n=c>>4, q=c&15;
        float s = bdc[n]+bdres[q];
        #pragma unroll
        for(int p=0;p<16;p++) s += be[q*16+p]*wdc[n*16+p];
        for(int j=0;j<256;j++) s += be[j]*Wd[j*16+q];
        g_bias2[c]=s;
    } else if(id<11776){
        int q=id-8704, n=q/96, t=q%96;
        float s=0.f;
        for(int j=0;j<256;j++) s += be[j]*Wl[(n*256+j)*96+t];
        atomicAdd(&g_biasL[t], s);
    } else if(id<12288){
        g_stats[id-11776]=0.f;
    }
}

// ---- transpose + symmetric split ----
__global__ __launch_bounds__(256) void k_transpose(const float* __restrict__ x){
    __shared__ float sm[512*21];
    int b = blockIdx.x;
    const float* xb = x + (size_t)b*512*21;
    for(int i=threadIdx.x;i<512*21;i+=256) sm[i]=xb[i];
    __syncthreads();
    for(int d=0;d<21;d++){
        size_t row = (size_t)(b*21+d);
        for(int l=threadIdx.x;l<512;l+=256) g_xt[row*512+l]=sm[l*21+d];
        int m = threadIdx.x;
        float a = sm[m*21+d], c = sm[(511-m)*21+d];
        g_xs[row*256+m]=a+c;
        g_xd[row*256+m]=a-c;
    }
}

// ---- generic tiled SGEMM, 64x64x16, 256 thr, 4x4/thread ----
template<int MODE>
__global__ __launch_bounds__(256) void k_gemm(const float* __restrict__ A, int lda,
        const float* __restrict__ Bm, int ldb, float* __restrict__ C, int ldc,
        int N, int K, const float* __restrict__ bias, const float* __restrict__ add,
        float* __restrict__ outp){
    __shared__ float As[16][68];
    __shared__ __align__(16) float Bs[16][64];
    int row0 = blockIdx.x*64, col0 = blockIdx.y*64;
    int tid = threadIdx.x, tx = tid&15, ty = tid>>4;
    float acc[4][4] = {};
    for(int kc=0;kc<K;kc+=16){
        #pragma unroll
        for(int it=0;it<4;it++){
            int mi = ty + it*16;
            As[tx][mi] = A[(size_t)(row0+mi)*lda + kc + tx];
        }
        #pragma unroll
        for(int it=0;it<4;it++){
            int l = tid + it*256, k = l>>6, n = l&63, col = col0+n;
            Bs[k][n] = (col<N) ? Bm[(size_t)(kc+k)*ldb + col] : 0.f;
        }
        __syncthreads();
        #pragma unroll
        for(int k=0;k<16;k++){
            float4 bv = *(const float4*)&Bs[k][tx*4];
            #pragma unroll
            for(int i=0;i<4;i++){
                float a = As[k][ty*4+i];
                acc[i][0]+=a*bv.x; acc[i][1]+=a*bv.y; acc[i][2]+=a*bv.z; acc[i][3]+=a*bv.w;
            }
        }
        __syncthreads();
    }
    #pragma unroll
    for(int i=0;i<4;i++){
        int row = row0 + ty*4 + i;
        #pragma unroll
        for(int j=0;j<4;j++){
            int col = col0 + tx*4 + j;
            if(col<N){
                float v = acc[i][j];
                if(MODE>=1) v += bias[col];
                if(MODE==2) v = gelu_f(v);
                if(MODE==3){
                    v += add[(size_t)row*96+col];
                    int b = row/21, d = row - b*21;
                    outp[(size_t)b*2016 + col*21 + d] = v;
                } else {
                    C[(size_t)row*ldc + col] = v;
                }
            }
        }
    }
}

// ---- energy (warp per row) ----
__global__ void k_energy(){
    int gw = (blockIdx.x*256+threadIdx.x)>>5, lane = threadIdx.x&31;
    const float* z = g_zsplit + (size_t)gw*512;
    float s=0.f;
    for(int i=lane;i<512;i+=32){ float x=z[i]; s+=x*x; }
    for(int o=16;o;o>>=1) s += __shfl_xor_sync(~0u,s,o);
    if(lane==0) g_energy[gw]=s;
}

// ---- median over 21 per batch ----
__global__ void k_median(){
    int b = blockIdx.x, t = threadIdx.x;
    __shared__ float e[21]; __shared__ float med;
    if(t<21) e[t]=g_energy[b*21+t];
    __syncwarp();
    if(t<21){
        float x=e[t]; int less=0,eq=0;
        for(int j=0;j<21;j++){ float y=e[j]; less += (y<x); eq += (y==x); }
        if(less<=10 && 10<less+eq) med=x;
    }
    __syncwarp();
    if(t<21) g_norme[b*21+t] = e[t]/(med+1e-6f);
}

// ---- global quantile (radix select, single block) ----
__global__ void k_quantile(const float* __restrict__ thr_p){
    __shared__ unsigned vals[5376];
    __shared__ unsigned hist[256];
    __shared__ unsigned s_pref; __shared__ int s_r;
    int tid = threadIdx.x;
    for(int i=tid;i<5376;i+=1024) vals[i]=__float_as_uint(g_norme[i]);
    float pos = thr_p[0]*5375.0f;
    int i0 = (int)floorf(pos); float fr = pos-(float)i0;
    int i1 = (i0+1<5376)? i0+1 : 5375;
    float rv0=0.f, rv1=0.f;
    for(int sel=0;sel<2;sel++){
        int r = sel? i1 : i0;
        unsigned prefix=0, msk=0;
        for(int shift=24;shift>=0;shift-=8){
            if(tid<256) hist[tid]=0;
            __syncthreads();
            for(int i=tid;i<5376;i+=1024){
                unsigned xv=vals[i];
                if((xv&msk)==prefix) atomicAdd(&hist[(xv>>shift)&255],1u);
            }
            __syncthreads();
            if(tid==0){
                unsigned acc=0;
                for(int bk=0;bk<256;bk++){
                    unsigned nb=hist[bk];
                    if(acc+nb>(unsigned)r){ s_pref=prefix|((unsigned)bk<<shift); s_r=r-(int)acc; break; }
                    acc+=nb;
                }
            }
            __syncthreads();
            prefix=s_pref; r=s_r; msk|=(255u<<shift);
            __syncthreads();
        }
        if(sel==0) rv0=__uint_as_float(prefix); else rv1=__uint_as_float(prefix);
    }
    if(tid==0) g_thr[0] = rv0 + fr*(rv1-rv0);
}

// ---- mask + scale + gelu + CH stats ----
__global__ void k_maskgelu(const float* __restrict__ wdct, const float* __restrict__ bdct){
    __shared__ float rs[2];
    int bd = blockIdx.x, tid = threadIdx.x;
    int d = bd - (bd/21)*21;
    float msk = (g_norme[bd] > g_thr[0]) ? 1.f : 0.f;
    float wd = wdct[d]*msk, b0 = bdct[d];
    if(tid<2) rs[tid]=0.f;
    __syncthreads();
    float ls=0.f, lq=0.f;
    for(int i=tid;i<512;i+=256){
        size_t o=(size_t)bd*512+i;
        float g2 = gelu_f(g_zsplit[o]*wd + b0);
        g_zsplit[o]=g2; ls+=g2; lq+=g2*g2;
    }
    atomicAdd(&rs[0],ls); atomicAdd(&rs[1],lq);
    __syncthreads();
    if(tid==0){ atomicAdd(&g_stats[CHB+d],rs[0]); atomicAdd(&g_stats[CHB+32+d],rs[1]); }
}

__global__ void k_finalize(int base, int nch, float invN,
                           const float* __restrict__ g, const float* __restrict__ b){
    int c = threadIdx.x; if(c>=nch) return;
    float s = g_stats[base+c], sq = g_stats[base+32+c];
    float m = s*invN, v = sq*invN - m*m;
    float a = g[c]*rsqrtf(v+1e-5f);
    g_stats[base+64+c]=a; g_stats[base+96+c]=b[c]-m*a;
}

// ---- recombine inverse DCT halves + BN fold + residual ----
__global__ void k_recombine(const float* __restrict__ wdct, const float* __restrict__ bdct){
    int bd = blockIdx.x, m = threadIdx.x;
    int d = bd - (bd/21)*21;
    float a = g_stats[CHB+64+d], c = g_stats[CHB+96+d];
    float wd = wdct[d], b0 = bdct[d];
    size_t r2 = (size_t)bd*256+m, r5 = (size_t)bd*512;
    float u = g_u[r2], v = g_v[r2];
    float x0 = g_xt[r5+m], x1 = g_xt[r5+511-m];
    g_z1[r5+m]     = a*(u+v) + c*(g_ce[m]+g_co[m]) + x0*wd + b0;
    g_z1[r5+511-m] = a*(u-v) + c*(g_ce[m]-g_co[m]) + x1*wd + b0;
}

// ---- patch branch: s1 + PN stats ----
__global__ void k_patch(){
    __shared__ float xr[512]; __shared__ float ss[32], sq2[32];
    int bd = blockIdx.x, tid = threadIdx.x;
    xr[tid]     = g_xt[(size_t)bd*512+tid];
    xr[tid+256] = g_xt[(size_t)bd*512+tid+256];
    if(tid<32){ ss[tid]=0.f; sq2[tid]=0.f; }
    __syncthreads();
    #pragma unroll
    for(int h=0;h<2;h++){
        int c = tid + h*256, n = c>>4, q = c&15;
        float s = g_bias2[c];
        const float* Mr = &g_Mpatch[n*256+q*16];
        const float* xp = &xr[n*16];
        #pragma unroll
        for(int i=0;i<16;i++) s += xp[i]*Mr[i];
        g_s1[(size_t)bd*512+c]=s;
        atomicAdd(&ss[n],s); atomicAdd(&sq2[n],s*s);
    }
    __syncthreads();
    if(tid<32){ atomicAdd(&g_stats[PNB+tid],ss[tid]); atomicAdd(&g_stats[PNB+32+tid],sq2[tid]); }
}

// ---- z2 = gelu(bn(s1)); zc_pre = conv3(z2); DN stats ----
__global__ void k_conv(const float* __restrict__ wdc1, const float* __restrict__ bdc1){
    __shared__ float z2s[512]; __shared__ float ss[32], sq2[32];
    int bd = blockIdx.x, tid = threadIdx.x;
    if(tid<32){ ss[tid]=0.f; sq2[tid]=0.f; }
    #pragma unroll
    for(int h=0;h<2;h++){
        int c = tid + h*256, n = c>>4;
        float a = g_stats[PNB+64+n], cc = g_stats[PNB+96+n];
        float g2 = gelu_f(g_s1[(size_t)bd*512+c]*a + cc);
        z2s[c]=g2; g_z2[(size_t)bd*512+c]=g2;
    }
    __syncthreads();
    #pragma unroll
    for(int h=0;h<2;h++){
        int c = tid + h*256, n = c>>4, q = c&15;
        float l = q>0 ? z2s[c-1] : 0.f;
        float m0 = z2s[c];
        float r = q<15 ? z2s[c+1] : 0.f;
        float zc = wdc1[n*3+0]*l + wdc1[n*3+1]*m0 + wdc1[n*3+2]*r + bdc1[n];
        g_zcp[(size_t)bd*512+c]=zc;
        atomicAdd(&ss[n],zc); atomicAdd(&sq2[n],zc*zc);
    }
    __syncthreads();
    if(tid<32){ atomicAdd(&g_stats[DNB+tid],ss[tid]); atomicAdd(&g_stats[DNB+32+tid],sq2[tid]); }
}

// ---- z2f = gelu(bn(zcp)) + z2 (in place into g_z2) ----
__global__ void k_z2f(){
    for(int idx=blockIdx.x*256+threadIdx.x; idx<BD*512; idx+=gridDim.x*256){
        int c = idx&511, n = c>>4;
        float a = g_stats[DNB+64+n], cc = g_stats[DNB+96+n];
        g_z2[idx] = gelu_f(g_zcp[idx]*a + cc) + g_z2[idx];
    }
}

// ---- attention dot (warp per row) + global stats ----
__global__ void k_att(const float* __restrict__ adwb){
    int gw = (blockIdx.x*256+threadIdx.x)>>5, lane = threadIdx.x&31;
    size_t r5 = (size_t)gw*512;
    float s=0.f;
    for(int i=lane;i<512;i+=32) s += g_z1[r5+i]*g_z2[r5+i]*g_attcoef[i];
    for(int o=16;o;o>>=1) s += __shfl_xor_sync(~0u,s,o);
    if(lane==0){
        float att = s + adwb[0];
        g_att[gw]=att;
        atomicAdd(&g_stats[ATT_SUM],att);
        atomicAdd(&g_stats[ATT_SQ],att*att);
    }
}

// ---- BN(att) + gelu + softmax over 21 ----
__global__ void k_softmax(const float* __restrict__ ag, const float* __restrict__ ab,
                          const float* __restrict__ cw, const float* __restrict__ cb){
    int b = blockIdx.x, t = threadIdx.x;
    float inv = 1.0f/5376.0f;
    float m = g_stats[ATT_SUM]*inv;
    float v = g_stats[ATT_SQ]*inv - m*m;
    float val = -1e30f;
    if(t<21){
        float a = g_att[b*21+t];
        a = ag[0]*(a-m)*rsqrtf(v+1e-5f)+ab[0];
        a = gelu_f(a);
        val = a*cw[0]+cb[0];
    }
    float mx = val;
    for(int o=16;o;o>>=1) mx = fmaxf(mx,__shfl_xor_sync(~0u,mx,o));
    float e = (t<21) ? expf(val-mx) : 0.f;
    float sum = e;
    for(int o=16;o;o>>=1) sum += __shfl_xor_sync(~0u,sum,o);
    if(t<21) g_att1[b*21+t] = e/sum;
}

// ---- zsum into g_zsplit ----
__global__ void k_zsum(){
    for(int idx=blockIdx.x*256+threadIdx.x; idx<BD*512; idx+=gridDim.x*256){
        int bd = idx>>9;
        float a1 = g_att1[bd];
        g_zsplit[idx] = g_z1[idx]*a1 + g_z2[idx]*(1.0f-a1);
    }
}

extern "C" void kernel_launch(void* const* d_in, const int* in_sizes, int n_in,
                              void* d_out, int out_size){
    const float* x        =(const float*)d_in[0];
    const float* w_dct    =(const float*)d_in[1];
    const float* b_dct    =(const float*)d_in[2];
    const float* W_embed  =(const float*)d_in[3];
    const float* b_embed  =(const float*)d_in[4];
    const float* W_linres =(const float*)d_in[5];
    const float* b_linres =(const float*)d_in[6];
    const float* W_dres   =(const float*)d_in[7];
    const float* b_dres   =(const float*)d_in[8];
    const float* w_dc     =(const float*)d_in[9];
    const float* b_dc     =(const float*)d_in[10];
    const float* w_dc1    =(const float*)d_in[11];
    const float* b_dc1    =(const float*)d_in[12];
    const float* g_dctn   =(const float*)d_in[13];
    const float* b_dctn   =(const float*)d_in[14];
    const float* g_patn   =(const float*)d_in[15];
    const float* b_patn   =(const float*)d_in[16];
    const float* g_depn   =(const float*)d_in[17];
    const float* b_depn   =(const float*)d_in[18];
    const float* thr_p    =(const float*)d_in[19];
    const float* W_m1     =(const float*)d_in[20];
    const float* b_m1     =(const float*)d_in[21];
    const float* W_m2     =(const float*)d_in[22];
    const float* b_m2     =(const float*)d_in[23];
    const float* a_dw_w   =(const float*)d_in[24];
    const float* a_dw_b   =(const float*)d_in[25];
    const float* a_cw     =(const float*)d_in[26];
    const float* a_cb     =(const float*)d_in[27];
    const float* a_g      =(const float*)d_in[28];
    const float* a_b      =(const float*)d_in[29];
    float* out = (float*)d_out;

    float *p_xs,*p_xd,*p_BE,*p_BO,*p_BPe,*p_BPo,*p_zs,*p_u,*p_v,*p_xt,*p_Wf,*p_bL,*p_zr,*p_h;
    cudaGetSymbolAddress((void**)&p_xs,  g_xs);
    cudaGetSymbolAddress((void**)&p_xd,  g_xd);
    cudaGetSymbolAddress((void**)&p_BE,  g_BE);
    cudaGetSymbolAddress((void**)&p_BO,  g_BO);
    cudaGetSymbolAddress((void**)&p_BPe, g_BPe);
    cudaGetSymbolAddress((void**)&p_BPo, g_BPo);
    cudaGetSymbolAddress((void**)&p_zs,  g_zsplit);
    cudaGetSymbolAddress((void**)&p_u,   g_u);
    cudaGetSymbolAddress((void**)&p_v,   g_v);
    cudaGetSymbolAddress((void**)&p_xt,  g_xt);
    cudaGetSymbolAddress((void**)&p_Wf,  g_Wfold);
    cudaGetSymbolAddress((void**)&p_bL,  g_biasL);
    cudaGetSymbolAddress((void**)&p_zr,  g_zres);
    cudaGetSymbolAddress((void**)&p_h,   g_h);

    k_mats<<<257,256>>>(a_dw_w);
    k_fold1<<<192,256>>>(W_embed,W_linres,b_linres);
    k_fold2<<<48,256>>>(W_embed,b_embed,W_linres,W_dres,b_dres,w_dc,b_dc);
    k_transpose<<<256,256>>>(x);

    dim3 gA(84,4), gB(84,2);
    // forward DCT (split)
    k_gemm<0><<<gA,256>>>(p_xs,256,p_BE,256,p_zs,    512,256,256,nullptr,nullptr,nullptr);
    k_gemm<0><<<gA,256>>>(p_xd,256,p_BO,256,p_zs+256,512,256,256,nullptr,nullptr,nullptr);
    k_energy<<<672,256>>>();
    k_median<<<256,32>>>();
    k_quantile<<<1,1024>>>(thr_p);
    k_maskgelu<<<BD,256>>>(w_dct,b_dct);
    k_finalize<<<1,32>>>(CHB,21,1.0f/131072.0f,g_dctn,b_dctn);
    // inverse DCT (split) with BN folded into recombine
    k_gemm<0><<<gA,256>>>(p_zs,    512,p_BPe,256,p_u,256,256,256,nullptr,nullptr,nullptr);
    k_gemm<0><<<gA,256>>>(p_zs+256,512,p_BPo,256,p_v,256,256,256,nullptr,nullptr,nullptr);
    k_recombine<<<BD,256>>>(w_dct,b_dct);
    // patch branch
    k_patch<<<BD,256>>>();
    k_finalize<<<1,32>>>(PNB,32,1.0f/86016.0f,g_patn,b_patn);
    k_conv<<<BD,256>>>(w_dc1,b_dc1);
    k_finalize<<<1,32>>>(DNB,32,1.0f/86016.0f,g_depn,b_depn);
    k_z2f<<<2688,256>>>();
    // attention + mix
    k_att<<<672,256>>>(a_dw_b);
    k_softmax<<<256,32>>>(a_g,a_b,a_cw,a_cb);
    k_zsum<<<2688,256>>>();
    // output GEMMs
    k_gemm<1><<<gB,256>>>(p_xt,512,p_Wf,96,p_zr,96,96,512,p_bL,nullptr,nullptr);
    k_gemm<2><<<gB,256>>>(p_zs,512,W_m1,96,p_h,96,96,512,b_m1,nullptr,nullptr);
    k_gemm<3><<<gB,256>>>(p_h,96,W_m2,96,nullptr,0,96,96,b_m2,p_zr,out);
}

// round 3
// speedup vs baseline: 1.3331x; 1.3331x over previous
#include <cuda_runtime.h>
#include <cuda_bf16.h>

#define BD 5376
#define CHB 0
#define PNB 128
#define DNB 256
#define ATT_SUM 384
#define ATT_SQ 385
#define PIF 3.14159265358979323846f

typedef unsigned long long ULL;
union F2U { ULL u; float2 f; };

__device__ float g_BE[65536], g_BO[65536], g_BPe[65536], g_BPo[65536];
__device__ float g_ce[256], g_co[256], g_attcoef[512];
__device__ float g_Wfold[49152], g_biasL[96], g_Mpatch[8192], g_bias2[512];
__device__ float g_xt[BD*512], g_xs[BD*256], g_xd[BD*256];
__device__ float g_zsplit[BD*512], g_u[BD*256], g_v[BD*256], g_z1[BD*512];
__device__ float g_s1[BD*512], g_z2[BD*512], g_zcp[BD*512];
__device__ float g_zres[BD*96], g_h[BD*96];
__device__ float g_energy[BD], g_norme[BD], g_att[BD], g_att1[BD];
__device__ float g_thr[2], g_stats[512];

__device__ __forceinline__ float gelu_f(float x){
    return 0.5f*x*(1.0f+erff(x*0.70710678118654752440f));
}
__device__ __forceinline__ ULL dup2(float x){ ULL r; asm("mov.b64 %0,{%1,%1};":"=l"(r):"f"(x)); return r; }
#define FFMA2(d,a,b) asm("fma.rn.f32x2 %0, %1, %2, %0;" : "+l"(d) : "l"(a), "l"(b))

// ---- DCT matrices + attcoef ----
__global__ void k_mats(const float* __restrict__ adw){
    int bm = blockIdx.x, t = threadIdx.x;
    if(bm < 256){
        int m = bm, j = t;
        float am = PIF*(float)(2*m+1);
        float ce = cosf(am*(float)(2*j)*(1.0f/1024.0f));
        float co = cosf(am*(float)(2*j+1)*(1.0f/1024.0f));
        g_BE[m*256+j] = 2.0f*ce;
        g_BO[m*256+j] = 2.0f*co;
        float bpe = ce*((j==0)?0.5f:1.0f)*(1.0f/512.0f);
        float bpo = co*(1.0f/512.0f);
        g_BPe[j*256+m] = bpe;
        g_BPo[j*256+m] = bpo;
        __shared__ float r1[256], r2[256];
        r1[t]=bpe; r2[t]=bpo; __syncthreads();
        for(int o=128;o>0;o>>=1){ if(t<o){ r1[t]+=r1[t+o]; r2[t]+=r2[t+o]; } __syncthreads(); }
        if(t==0){ g_ce[m]=r1[0]; g_co[m]=r2[0]; }
    } else {
        float rL = sqrtf(512.0f);
        for(int m=t; m<512; m+=256){
            float am = PIF*(float)(2*m+1);
            float s = 0.f;
            for(int k=0;k<5;k++){
                float c = 2.0f*cosf(am*(float)k*(1.0f/1024.0f));
                float so = (k==0)? (0.5f/rL) : (0.5f*sqrtf(2.0f)/rL);
                s += adw[k]*so*c;
            }
            g_attcoef[m]=s;
        }
    }
}

// ---- weight folding ----
__global__ void k_fold1(const float* __restrict__ We, const float* __restrict__ Wl,
                        const float* __restrict__ bl){
    int id = blockIdx.x*256+threadIdx.x;
    if(id<96) g_biasL[id]=bl[id];
    if(id>=49152) return;
    int c=id/96, t=id%96, n=c>>4, p=c&15;
    float s=0.f;
    for(int j=0;j<256;j++) s += We[p*256+j]*Wl[(n*256+j)*96+t];
    g_Wfold[id]=s;
}

__global__ void k_fold2(const float* __restrict__ We, const float* __restrict__ be,
                        const float* __restrict__ Wl, const float* __restrict__ Wd,
                        const float* __restrict__ bdres, const float* __restrict__ wdc,
                        const float* __restrict__ bdc){
    int id = blockIdx.x*256+threadIdx.x;
    if(id<8192){
        int n=id/256, q=(id>>4)&15, i=id&15;
        float s=0.f;
        #pragma unroll
        for(int p=0;p<16;p++) s += We[i*256+q*16+p]*wdc[n*16+p];
        for(int j=0;j<256;j++) s += We[i*256+j]*Wd[j*16+q];
        g_Mpatch[id]=s;
    } else if(id<8704){
        int c=id-8192, n=c>>4, q=c&15;
        float s = bdc[n]+bdres[q];
        #pragma unroll
        for(int p=0;p<16;p++) s += be[q*16+p]*wdc[n*16+p];
        for(int j=0;j<256;j++) s += be[j]*Wd[j*16+q];
        g_bias2[c]=s;
    } else if(id<11776){
        int q=id-8704, n=q/96, t=q%96;
        float s=0.f;
        for(int j=0;j<256;j++) s += be[j]*Wl[(n*256+j)*96+t];
        atomicAdd(&g_biasL[t], s);
    } else if(id<12288){
        g_stats[id-11776]=0.f;
    } else if(id<12288+BD){
        g_energy[id-12288]=0.f;
    }
}

// ---- transpose + symmetric split ----
__global__ __launch_bounds__(256) void k_transpose(const float* __restrict__ x){
    __shared__ float sa[128*21], sb[128*21];
    int b = blockIdx.x, c = blockIdx.y, tid = threadIdx.x;
    int l0 = c*128, l1 = (3-c)*128;
    const float* xb = x + (size_t)b*512*21;
    for(int i=tid;i<128*21;i+=256){ sa[i]=xb[l0*21+i]; sb[i]=xb[l1*21+i]; }
    __syncthreads();
    int t = tid&127;
    for(int d=(tid>>7); d<21; d+=2){
        size_t row = (size_t)(b*21+d);
        float va = sa[t*21+d], vb = sb[(127-t)*21+d], vb2 = sb[t*21+d];
        g_xt[row*512+l0+t]=va;
        g_xt[row*512+l1+t]=vb2;
        g_xs[row*256+l0+t]=va+vb;
        g_xd[row*256+l0+t]=va-vb;
    }
}

// ---- FFMA2 SGEMM: 128x64 tile, 256 thr, 8x4/thread ----
// EPI: 0=store, 1=store+row-energy, 2=bias, 3=bias+gelu, 4=bias+add+scatter-out
template<int EPI, bool AZ>
__global__ __launch_bounds__(256) void k_gemm(
    const float* __restrict__ A0, const float* __restrict__ A1, int lda,
    const float* __restrict__ B0, const float* __restrict__ B1, int ldb,
    float* __restrict__ C0, float* __restrict__ C1, int ldc,
    int N, int K,
    const float* __restrict__ bias, const float* __restrict__ add,
    float* __restrict__ outp)
{
    const float* A  = blockIdx.z ? A1 : A0;
    const float* Bm = blockIdx.z ? B1 : B0;
    float* C        = blockIdx.z ? C1 : C0;
    __shared__ ULL As2[16][129];
    __shared__ __align__(16) float Bs[16][64];
    int row0 = blockIdx.x*128, col0 = blockIdx.y*64;
    int tid = threadIdx.x, tx = tid&15, ty = tid>>4;
    ULL acc[8][2] = {};
    float w8[8];
    if(AZ){
        #pragma unroll
        for(int it=0;it<8;it++) w8[it] = g_att1[row0 + ty + it*16];
    }
    for(int kc=0;kc<K;kc+=16){
        #pragma unroll
        for(int it=0;it<8;it++){
            int m = ty + it*16;
            int row = row0 + m;
            float a;
            if(AZ){
                size_t o = (size_t)row*512 + kc + tx;
                a = g_z1[o]*w8[it] + g_z2[o]*(1.0f - w8[it]);
            } else {
                a = A[(size_t)row*lda + kc + tx];
            }
            As2[tx][m] = dup2(a);
        }
        #pragma unroll
        for(int it=0;it<4;it++){
            int l = tid + it*256, k = l>>6, n = l&63, col = col0+n;
            Bs[k][n] = (col<N) ? Bm[(size_t)(kc+k)*ldb + col] : 0.f;
        }
        __syncthreads();
        #pragma unroll
        for(int k=0;k<16;k++){
            const ULL* ap = &As2[k][ty*8];
            ULL av[8];
            #pragma unroll
            for(int i=0;i<8;i++) av[i]=ap[i];
            ulonglong2 bb = *(const ulonglong2*)&Bs[k][tx*4];
            #pragma unroll
            for(int i=0;i<8;i++){ FFMA2(acc[i][0],av[i],bb.x); FFMA2(acc[i][1],av[i],bb.y); }
        }
        __syncthreads();
    }
    int col = col0 + tx*4;
    #pragma unroll
    for(int i=0;i<8;i++){
        int row = row0 + ty*8 + i;
        F2U v0, v1; v0.u = acc[i][0]; v1.u = acc[i][1];
        if(EPI<=1){
            *(float2*)&C[(size_t)row*ldc + col]     = v0.f;
            *(float2*)&C[(size_t)row*ldc + col + 2] = v1.f;
            if(EPI==1){
                float e = v0.f.x*v0.f.x + v0.f.y*v0.f.y + v1.f.x*v1.f.x + v1.f.y*v1.f.y;
                #pragma unroll
                for(int o=8;o;o>>=1) e += __shfl_xor_sync(0xffffffffu, e, o);
                if(tx==0) atomicAdd(&g_energy[row], e);
            }
        } else {
            if(col<N){
                v0.f.x += bias[col];   v0.f.y += bias[col+1];
                if(EPI==3){ v0.f.x = gelu_f(v0.f.x); v0.f.y = gelu_f(v0.f.y); }
                if(EPI==4){
                    int b = row/21, d = row - b*21;
                    float o0 = v0.f.x + add[(size_t)row*96+col];
                    float o1 = v0.f.y + add[(size_t)row*96+col+1];
                    outp[(size_t)b*2016 + (col  )*21 + d] = o0;
                    outp[(size_t)b*2016 + (col+1)*21 + d] = o1;
                } else {
                    *(float2*)&C[(size_t)row*ldc + col] = v0.f;
                }
            }
            if(col+2<N){
                v1.f.x += bias[col+2]; v1.f.y += bias[col+3];
                if(EPI==3){ v1.f.x = gelu_f(v1.f.x); v1.f.y = gelu_f(v1.f.y); }
                if(EPI==4){
                    int b = row/21, d = row - b*21;
                    float o2 = v1.f.x + add[(size_t)row*96+col+2];
                    float o3 = v1.f.y + add[(size_t)row*96+col+3];
                    outp[(size_t)b*2016 + (col+2)*21 + d] = o2;
                    outp[(size_t)b*2016 + (col+3)*21 + d] = o3;
                } else {
                    *(float2*)&C[(size_t)row*ldc + col + 2] = v1.f;
                }
            }
        }
    }
}

// ---- median over 21 per batch ----
__global__ void k_median(){
    int b = blockIdx.x, t = threadIdx.x;
    __shared__ float e[21]; __shared__ float med;
    if(t<21) e[t]=g_energy[b*21+t];
    __syncwarp();
    if(t<21){
        float x=e[t]; int less=0,eq=0;
        for(int j=0;j<21;j++){ float y=e[j]; less += (y<x); eq += (y==x); }
        if(less<=10 && 10<less+eq) med=x;
    }
    __syncwarp();
    if(t<21) g_norme[b*21+t] = e[t]/(med+1e-6f);
}

// ---- global quantile (radix select; 2 blocks, one per rank) ----
__global__ void k_quantile(const float* __restrict__ thr_p){
    __shared__ unsigned vals[5376];
    __shared__ unsigned hist[256];
    __shared__ unsigned s_pref; __shared__ int s_r;
    int tid = threadIdx.x;
    for(int i=tid;i<5376;i+=1024) vals[i]=__float_as_uint(g_norme[i]);
    float pos = thr_p[0]*5375.0f;
    int i0 = (int)floorf(pos);
    int r = blockIdx.x ? ((i0+1<5376)?i0+1:5375) : i0;
    unsigned prefix=0, msk=0;
    for(int shift=24;shift>=0;shift-=8){
        if(tid<256) hist[tid]=0;
        __syncthreads();
        for(int i=tid;i<5376;i+=1024){
            unsigned xv=vals[i];
            if((xv&msk)==prefix) atomicAdd(&hist[(xv>>shift)&255],1u);
        }
        __syncthreads();
        if(tid==0){
            unsigned acc=0;
            for(int bk=0;bk<256;bk++){
                unsigned nb=hist[bk];
                if(acc+nb>(unsigned)r){ s_pref=prefix|((unsigned)bk<<shift); s_r=r-(int)acc; break; }
                acc+=nb;
            }
        }
        __syncthreads();
        prefix=s_pref; r=s_r; msk|=(255u<<shift);
        __syncthreads();
    }
    if(tid==0) g_thr[blockIdx.x]=__uint_as_float(prefix);
}

// ---- mask + scale + gelu + CH stats ----
__global__ void k_maskgelu(const float* __restrict__ wdct, const float* __restrict__ bdct,
                           const float* __restrict__ thr_p){
    __shared__ float rs[2];
    int bd = blockIdx.x, tid = threadIdx.x;
    int d = bd - (bd/21)*21;
    float pos = thr_p[0]*5375.0f;
    float fr = pos - floorf(pos);
    float thr = g_thr[0] + fr*(g_thr[1]-g_thr[0]);
    float msk = (g_norme[bd] > thr) ? 1.f : 0.f;
    float wd = wdct[d]*msk, b0 = bdct[d];
    if(tid<2) rs[tid]=0.f;
    __syncthreads();
    float ls=0.f, lq=0.f;
    #pragma unroll
    for(int h=0;h<2;h++){
        size_t o=(size_t)bd*512 + tid + h*256;
        float g2 = gelu_f(g_zsplit[o]*wd + b0);
        g_zsplit[o]=g2; ls+=g2; lq+=g2*g2;
    }
    #pragma unroll
    for(int o=16;o;o>>=1){ ls += __shfl_xor_sync(~0u,ls,o); lq += __shfl_xor_sync(~0u,lq,o); }
    if((tid&31)==0){ atomicAdd(&rs[0],ls); atomicAdd(&rs[1],lq); }
    __syncthreads();
    if(tid==0){ atomicAdd(&g_stats[CHB+d],rs[0]); atomicAdd(&g_stats[CHB+32+d],rs[1]); }
}

__global__ void k_finalize(int base, int nch, float invN,
                           const float* __restrict__ g, const float* __restrict__ b){
    int c = threadIdx.x; if(c>=nch) return;
    float s = g_stats[base+c], sq = g_stats[base+32+c];
    float m = s*invN, v = sq*invN - m*m;
    float a = g[c]*rsqrtf(v+1e-5f);
    g_stats[base+64+c]=a; g_stats[base+96+c]=b[c]-m*a;
}

// ---- fused: recombine inverse-DCT + BN fold + residual, then patch branch + PN stats ----
__global__ __launch_bounds__(256) void k_recpatch(const float* __restrict__ wdct,
                                                  const float* __restrict__ bdct){
    __shared__ float xr[512]; __shared__ float ps[32], pq[32];
    int bd = blockIdx.x, tid = threadIdx.x;
    int d = bd - (bd/21)*21;
    size_t r5 = (size_t)bd*512;
    xr[tid]     = g_xt[r5+tid];
    xr[tid+256] = g_xt[r5+tid+256];
    if(tid<32){ ps[tid]=0.f; pq[tid]=0.f; }
    __syncthreads();
    {
        float a = g_stats[CHB+64+d], c = g_stats[CHB+96+d];
        float wd = wdct[d], b0 = bdct[d];
        size_t r2 = (size_t)bd*256+tid;
        float u = g_u[r2], v = g_v[r2];
        g_z1[r5+tid]     = a*(u+v) + c*(g_ce[tid]+g_co[tid]) + xr[tid]*wd + b0;
        g_z1[r5+511-tid] = a*(u-v) + c*(g_ce[tid]-g_co[tid]) + xr[511-tid]*wd + b0;
    }
    #pragma unroll
    for(int h=0;h<2;h++){
        int c2 = tid + h*256, n = c2>>4, q = c2&15;
        float s = g_bias2[c2];
        const float* Mr = &g_Mpatch[n*256+q*16];
        const float* xp = &xr[n*16];
        #pragma unroll
        for(int i=0;i<16;i++) s += xp[i]*Mr[i];
        g_s1[r5+c2]=s;
        float sq = s*s;
        #pragma unroll
        for(int o=8;o;o>>=1){ s += __shfl_xor_sync(~0u,s,o); sq += __shfl_xor_sync(~0u,sq,o); }
        if((tid&15)==0){ atomicAdd(&ps[n],s); atomicAdd(&pq[n],sq); }
    }
    __syncthreads();
    if(tid<32){ atomicAdd(&g_stats[PNB+tid],ps[tid]); atomicAdd(&g_stats[PNB+32+tid],pq[tid]); }
}

// ---- z2 = gelu(bn(s1)); zc_pre = conv3(z2); DN stats ----
__global__ void k_conv(const float* __restrict__ wdc1, const float* __restrict__ bdc1){
    __shared__ float z2s[512]; __shared__ float ss[32], sq2[32];
    int bd = blockIdx.x, tid = threadIdx.x;
    size_t r5 = (size_t)bd*512;
    if(tid<32){ ss[tid]=0.f; sq2[tid]=0.f; }
    #pragma unroll
    for(int h=0;h<2;h++){
        int c = tid + h*256, n = c>>4;
        float a = g_stats[PNB+64+n], cc = g_stats[PNB+96+n];
        float g2 = gelu_f(g_s1[r5+c]*a + cc);
        z2s[c]=g2; g_z2[r5+c]=g2;
    }
    __syncthreads();
    #pragma unroll
    for(int h=0;h<2;h++){
        int c = tid + h*256, n = c>>4, q = c&15;
        float l = q>0 ? z2s[c-1] : 0.f;
        float m0 = z2s[c];
        float r = q<15 ? z2s[c+1] : 0.f;
        float zc = wdc1[n*3+0]*l + wdc1[n*3+1]*m0 + wdc1[n*3+2]*r + bdc1[n];
        g_zcp[r5+c]=zc;
        float s=zc, sq=zc*zc;
        #pragma unroll
        for(int o=8;o;o>>=1){ s += __shfl_xor_sync(~0u,s,o); sq += __shfl_xor_sync(~0u,sq,o); }
        if((tid&15)==0){ atomicAdd(&ss[n],s); atomicAdd(&sq2[n],sq); }
    }
    __syncthreads();
    if(tid<32){ atomicAdd(&g_stats[DNB+tid],ss[tid]); atomicAdd(&g_stats[DNB+32+tid],sq2[tid]); }
}

// ---- fused: z2f = gelu(bn(zcp)) + z2 (into g_z2), attention dot + stats ----
__global__ void k_z2att(const float* __restrict__ adwb){
    __shared__ float red[8];
    int bd = blockIdx.x, tid = threadIdx.x;
    size_t r5 = (size_t)bd*512;
    float dot = 0.f;
    #pragma unroll
    for(int h=0;h<2;h++){
        int c = tid + h*256, n = c>>4;
        float a = g_stats[DNB+64+n], cc = g_stats[DNB+96+n];
        float z2f = gelu_f(g_zcp[r5+c]*a + cc) + g_z2[r5+c];
        g_z2[r5+c] = z2f;
        dot += g_z1[r5+c]*z2f*g_attcoef[c];
    }
    #pragma unroll
    for(int o=16;o;o>>=1) dot += __shfl_xor_sync(~0u,dot,o);
    if((tid&31)==0) red[tid>>5]=dot;
    __syncthreads();
    if(tid<8){
        float s = red[tid];
        #pragma unroll
        for(int o=4;o;o>>=1) s += __shfl_xor_sync(0xffu,s,o);
        if(tid==0){
            float att = s + adwb[0];
            g_att[bd]=att;
            atomicAdd(&g_stats[ATT_SUM],att);
            atomicAdd(&g_stats[ATT_SQ],att*att);
        }
    }
}

// ---- BN(att) + gelu + softmax over 21 ----
__global__ void k_softmax(const float* __restrict__ ag, const float* __restrict__ ab,
                          const float* __restrict__ cw, const float* __restrict__ cb){
    int b = blockIdx.x, t = threadIdx.x;
    float inv = 1.0f/5376.0f;
    float m = g_stats[ATT_SUM]*inv;
    float v = g_stats[ATT_SQ]*inv - m*m;
    float val = -1e30f;
    if(t<21){
        float a = g_att[b*21+t];
        a = ag[0]*(a-m)*rsqrtf(v+1e-5f)+ab[0];
        a = gelu_f(a);
        val = a*cw[0]+cb[0];
    }
    float mx = val;
    for(int o=16;o;o>>=1) mx = fmaxf(mx,__shfl_xor_sync(~0u,mx,o));
    float e = (t<21) ? expf(val-mx) : 0.f;
    float sum = e;
    for(int o=16;o;o>>=1) sum += __shfl_xor_sync(~0u,sum,o);
    if(t<21) g_att1[b*21+t] = e/sum;
}

extern "C" void kernel_launch(void* const* d_in, const int* in_sizes, int n_in,
                              void* d_out, int out_size){
    const float* x        =(const float*)d_in[0];
    const float* w_dct    =(const float*)d_in[1];
    const float* b_dct    =(const float*)d_in[2];
    const float* W_embed  =(const float*)d_in[3];
    const float* b_embed  =(const float*)d_in[4];
    const float* W_linres =(const float*)d_in[5];
    const float* b_linres =(const float*)d_in[6];
    const float* W_dres   =(const float*)d_in[7];
    const float* b_dres   =(const float*)d_in[8];
    const float* w_dc     =(const float*)d_in[9];
    const float* b_dc     =(const float*)d_in[10];
    const float* w_dc1    =(const float*)d_in[11];
    const float* b_dc1    =(const float*)d_in[12];
    const float* g_dctn   =(const float*)d_in[13];
    const float* b_dctn   =(const float*)d_in[14];
    const float* g_patn   =(const float*)d_in[15];
    const float* b_patn   =(const float*)d_in[16];
    const float* g_depn   =(const float*)d_in[17];
    const float* b_depn   =(const float*)d_in[18];
    const float* thr_p    =(const float*)d_in[19];
    const float* W_m1     =(const float*)d_in[20];
    const float* b_m1     =(const float*)d_in[21];
    const float* W_m2     =(const float*)d_in[22];
    const float* b_m2     =(const float*)d_in[23];
    const float* a_dw_w   =(const float*)d_in[24];
    const float* a_dw_b   =(const float*)d_in[25];
    const float* a_cw     =(const float*)d_in[26];
    const float* a_cb     =(const float*)d_in[27];
    const float* a_g      =(const float*)d_in[28];
    const float* a_b      =(const float*)d_in[29];
    float* out = (float*)d_out;

    float *p_xs,*p_xd,*p_BE,*p_BO,*p_BPe,*p_BPo,*p_zs,*p_u,*p_v,*p_xt,*p_Wf,*p_bL,*p_zr,*p_h;
    cudaGetSymbolAddress((void**)&p_xs,  g_xs);
    cudaGetSymbolAddress((void**)&p_xd,  g_xd);
    cudaGetSymbolAddress((void**)&p_BE,  g_BE);
    cudaGetSymbolAddress((void**)&p_BO,  g_BO);
    cudaGetSymbolAddress((void**)&p_BPe, g_BPe);
    cudaGetSymbolAddress((void**)&p_BPo, g_BPo);
    cudaGetSymbolAddress((void**)&p_zs,  g_zsplit);
    cudaGetSymbolAddress((void**)&p_u,   g_u);
    cudaGetSymbolAddress((void**)&p_v,   g_v);
    cudaGetSymbolAddress((void**)&p_xt,  g_xt);
    cudaGetSymbolAddress((void**)&p_Wf,  g_Wfold);
    cudaGetSymbolAddress((void**)&p_bL,  g_biasL);
    cudaGetSymbolAddress((void**)&p_zr,  g_zres);
    cudaGetSymbolAddress((void**)&p_h,   g_h);

    k_mats<<<257,256>>>(a_dw_w);
    k_fold1<<<192,256>>>(W_embed,W_linres,b_linres);
    k_fold2<<<70,256>>>(W_embed,b_embed,W_linres,W_dres,b_dres,w_dc,b_dc);
    k_transpose<<<dim3(256,2),256>>>(x);

    // forward DCT pair (even/odd) + fused row-energy
    k_gemm<1,false><<<dim3(42,4,2),256>>>(p_xs,p_xd,256, p_BE,p_BO,256,
                                          p_zs,p_zs+256,512, 256,256, nullptr,nullptr,nullptr);
    k_median<<<256,32>>>();
    k_quantile<<<2,1024>>>(thr_p);
    k_maskgelu<<<BD,256>>>(w_dct,b_dct,thr_p);
    k_finalize<<<1,32>>>(CHB,21,1.0f/131072.0f,g_dctn,b_dctn);
    // inverse DCT pair
    k_gemm<0,false><<<dim3(42,4,2),256>>>(p_zs,p_zs+256,512, p_BPe,p_BPo,256,
                                          p_u,p_v,256, 256,256, nullptr,nullptr,nullptr);
    k_recpatch<<<BD,256>>>(w_dct,b_dct);
    k_finalize<<<1,32>>>(PNB,32,1.0f/86016.0f,g_patn,b_patn);
    k_conv<<<BD,256>>>(w_dc1,b_dc1);
    k_finalize<<<1,32>>>(DNB,32,1.0f/86016.0f,g_depn,b_depn);
    k_z2att<<<BD,256>>>(a_dw_b);
    k_softmax<<<256,32>>>(a_g,a_b,a_cw,a_cb);
    // output GEMMs
    k_gemm<2,false><<<dim3(42,2,1),256>>>(p_xt,p_xt,512, p_Wf,p_Wf,96,
                                          p_zr,p_zr,96, 96,512, p_bL,nullptr,nullptr);
    k_gemm<3,true><<<dim3(42,2,1),256>>>(nullptr,nullptr,512, W_m1,W_m1,96,
                                         p_h,p_h,96, 96,512, b_m1,nullptr,nullptr);
    k_gemm<4,false><<<dim3(42,2,1),256>>>(p_h,p_h,96, W_m2,W_m2,96,
                                          nullptr,nullptr,96, 96,96, b_m2,p_zr,out);
}

// round 4
// speedup vs baseline: 1.4930x; 1.1200x over previous
#include <cuda_runtime.h>
#include <cuda_bf16.h>

#define BD 5376
#define CHB 0
#define PNB 128
#define DNB 256
#define ATT_SUM 384
#define ATT_SQ 385
#define PIF 3.14159265358979323846f

typedef unsigned long long ULL;
union F2U { ULL u; float2 f; };

__device__ float g_BE[65536], g_BO[65536], g_BPe[65536], g_BPo[65536];
__device__ float g_ce[256], g_co[256], g_attcoef[512];
__device__ float g_Wfold[49152], g_biasL[96], g_Mpatch[8192], g_bias2[512];
__device__ float g_xt[BD*512], g_xs[BD*256], g_xd[BD*256];
__device__ float g_zsplit[BD*512], g_u[BD*256], g_v[BD*256], g_z1[BD*512];
__device__ float g_s1[BD*512], g_z2[BD*512], g_zcp[BD*512];
__device__ float g_zres[BD*96], g_h[BD*96];
__device__ float g_energy[BD], g_norme[BD], g_att[BD], g_att1[BD];
__device__ float g_thr[2], g_stats[512];

__device__ __forceinline__ float gelu_f(float x){
    return 0.5f*x*(1.0f+erff(x*0.70710678118654752440f));
}
__device__ __forceinline__ ULL dup2(float x){ ULL r; asm("mov.b64 %0,{%1,%1};":"=l"(r):"f"(x)); return r; }
#define FFMA2(d,a,b) asm("fma.rn.f32x2 %0, %1, %2, %0;" : "+l"(d) : "l"(a), "l"(b))

// ---- DCT matrices + attcoef ----
__global__ void k_mats(const float* __restrict__ adw){
    int bm = blockIdx.x, t = threadIdx.x;
    if(bm < 256){
        int m = bm, j = t;
        float am = PIF*(float)(2*m+1);
        float ce = cosf(am*(float)(2*j)*(1.0f/1024.0f));
        float co = cosf(am*(float)(2*j+1)*(1.0f/1024.0f));
        g_BE[m*256+j] = 2.0f*ce;
        g_BO[m*256+j] = 2.0f*co;
        float bpe = ce*((j==0)?0.5f:1.0f)*(1.0f/512.0f);
        float bpo = co*(1.0f/512.0f);
        g_BPe[j*256+m] = bpe;
        g_BPo[j*256+m] = bpo;
        __shared__ float r1[256], r2[256];
        r1[t]=bpe; r2[t]=bpo; __syncthreads();
        for(int o=128;o>0;o>>=1){ if(t<o){ r1[t]+=r1[t+o]; r2[t]+=r2[t+o]; } __syncthreads(); }
        if(t==0){ g_ce[m]=r1[0]; g_co[m]=r2[0]; }
    } else {
        float rL = sqrtf(512.0f);
        for(int m=t; m<512; m+=256){
            float am = PIF*(float)(2*m+1);
            float s = 0.f;
            for(int k=0;k<5;k++){
                float c = 2.0f*cosf(am*(float)k*(1.0f/1024.0f));
                float so = (k==0)? (0.5f/rL) : (0.5f*sqrtf(2.0f)/rL);
                s += adw[k]*so*c;
            }
            g_attcoef[m]=s;
        }
    }
}

// ---- weight folding ----
__global__ void k_fold1(const float* __restrict__ We, const float* __restrict__ Wl,
                        const float* __restrict__ bl){
    int id = blockIdx.x*256+threadIdx.x;
    if(id<96) g_biasL[id]=bl[id];
    if(id>=49152) return;
    int c=id/96, t=id%96, n=c>>4, p=c&15;
    float s=0.f;
    for(int j=0;j<256;j++) s += We[p*256+j]*Wl[(n*256+j)*96+t];
    g_Wfold[id]=s;
}

__global__ void k_fold2(const float* __restrict__ We, const float* __restrict__ be,
                        const float* __restrict__ Wl, const float* __restrict__ Wd,
                        const float* __restrict__ bdres, const float* __restrict__ wdc,
                        const float* __restrict__ bdc){
    int id = blockIdx.x*256+threadIdx.x;
    if(id<8192){
        int n=id/256, q=(id>>4)&15, i=id&15;
        float s=0.f;
        #pragma unroll
        for(int p=0;p<16;p++) s += We[i*256+q*16+p]*wdc[n*16+p];
        for(int j=0;j<256;j++) s += We[i*256+j]*Wd[j*16+q];
        g_Mpatch[id]=s;
    } else if(id<8704){
        int c=id-8192, n=c>>4, q=c&15;
        float s = bdc[n]+bdres[q];
        #pragma unroll
        for(int p=0;p<16;p++) s += be[q*16+p]*wdc[n*16+p];
        for(int j=0;j<256;j++) s += be[j]*Wd[j*16+q];
        g_bias2[c]=s;
    } else if(id<11776){
        int q=id-8704, n=q/96, t=q%96;
        float s=0.f;
        for(int j=0;j<256;j++) s += be[j]*Wl[(n*256+j)*96+t];
        atomicAdd(&g_biasL[t], s);
    } else if(id<12288){
        g_stats[id-11776]=0.f;
    }
}

// ---- transpose + symmetric split ----
__global__ __launch_bounds__(256) void k_transpose(const float* __restrict__ x){
    __shared__ float sa[128*21], sb[128*21];
    int b = blockIdx.x, c = blockIdx.y, tid = threadIdx.x;
    int l0 = c*128, l1 = (3-c)*128;
    const float* xb = x + (size_t)b*512*21;
    for(int i=tid;i<128*21;i+=256){ sa[i]=xb[l0*21+i]; sb[i]=xb[l1*21+i]; }
    __syncthreads();
    int t = tid&127;
    for(int d=(tid>>7); d<21; d+=2){
        size_t row = (size_t)(b*21+d);
        float va = sa[t*21+d], vb = sb[(127-t)*21+d], vb2 = sb[t*21+d];
        g_xt[row*512+l0+t]=va;
        g_xt[row*512+l1+t]=vb2;
        g_xs[row*256+l0+t]=va+vb;
        g_xd[row*256+l0+t]=va-vb;
    }
}

// ---- DCT GEMM: M64 x N128, K=256, 256 thr (8x32), 8 rows x 4 cols/thread ----
__global__ __launch_bounds__(256,3) void k_gemmA(
    const float* __restrict__ A0, const float* __restrict__ A1, int lda,
    const float* __restrict__ B0, const float* __restrict__ B1,
    float* __restrict__ C0, float* __restrict__ C1, int ldc)
{
    const float* A  = blockIdx.z ? A1 : A0;
    const float* Bm = blockIdx.z ? B1 : B0;
    float* C        = blockIdx.z ? C1 : C0;
    __shared__ float As[16][66];
    __shared__ __align__(16) float Bs[16][128];
    int row0 = blockIdx.x*64, col0 = blockIdx.y*128;
    int tid = threadIdx.x, tx = tid&31, ty = tid>>5;
    int am = tid&63, ak = (tid>>6)*4;
    int bn = (tid&31)*4, bk = tid>>5;
    ULL acc[4][4] = {};
    for(int kc=0;kc<256;kc+=16){
        float4 a4 = *(const float4*)&A[(size_t)(row0+am)*lda + kc + ak];
        As[ak+0][am]=a4.x; As[ak+1][am]=a4.y; As[ak+2][am]=a4.z; As[ak+3][am]=a4.w;
        float4 b0 = *(const float4*)&Bm[(size_t)(kc+bk)*256 + col0 + bn];
        float4 b1 = *(const float4*)&Bm[(size_t)(kc+bk+8)*256 + col0 + bn];
        *(float4*)&Bs[bk][bn]   = b0;
        *(float4*)&Bs[bk+8][bn] = b1;
        __syncthreads();
        #pragma unroll
        for(int k=0;k<16;k++){
            ULL av[4];
            #pragma unroll
            for(int rp=0;rp<4;rp++) av[rp] = *(const ULL*)&As[k][ty*8+2*rp];
            float4 bx = *(const float4*)&Bs[k][tx*4];
            ULL bd0=dup2(bx.x), bd1=dup2(bx.y), bd2=dup2(bx.z), bd3=dup2(bx.w);
            #pragma unroll
            for(int rp=0;rp<4;rp++){
                FFMA2(acc[rp][0],av[rp],bd0);
                FFMA2(acc[rp][1],av[rp],bd1);
                FFMA2(acc[rp][2],av[rp],bd2);
                FFMA2(acc[rp][3],av[rp],bd3);
            }
        }
        __syncthreads();
    }
    int col = col0 + tx*4;
    #pragma unroll
    for(int rp=0;rp<4;rp++){
        int r = row0 + ty*8 + 2*rp;
        F2U t0,t1,t2,t3; t0.u=acc[rp][0]; t1.u=acc[rp][1]; t2.u=acc[rp][2]; t3.u=acc[rp][3];
        float4 lo = make_float4(t0.f.x,t1.f.x,t2.f.x,t3.f.x);
        float4 hi = make_float4(t0.f.y,t1.f.y,t2.f.y,t3.f.y);
        *(float4*)&C[(size_t)r*ldc + col]     = lo;
        *(float4*)&C[(size_t)(r+1)*ldc + col] = hi;
    }
}

// ---- Output GEMM: M32 x N96(padded 128), 256 thr (8x32), 4 rows x 4 cols/thread ----
struct Cfg { const float* A; const float* B; float* C; const float* bias;
             int lda; int K; int epi; int az; };

__global__ __launch_bounds__(256,4) void k_gemmB(Cfg c0, Cfg c1,
        const float* __restrict__ addp, float* __restrict__ outp)
{
    Cfg c = blockIdx.z ? c1 : c0;
    __shared__ float As[16][34];
    __shared__ __align__(16) float Bs[16][128];
    int row0 = blockIdx.x*32;
    int tid = threadIdx.x, tx = tid&31, ty = tid>>5;
    int am = tid&31, ak = (tid>>5)*2;
    int bn = (tid&31)*4, bk = tid>>5;
    ULL acc[2][4] = {};
    float w = 0.f;
    if(c.az) w = g_att1[row0+am];
    for(int kc=0;kc<c.K;kc+=16){
        float2 a2;
        if(c.az){
            size_t o = (size_t)(row0+am)*512 + kc + ak;
            float2 z1v = *(const float2*)&g_z1[o];
            float2 z2v = *(const float2*)&g_z2[o];
            a2.x = z1v.x*w + z2v.x*(1.0f-w);
            a2.y = z1v.y*w + z2v.y*(1.0f-w);
        } else {
            a2 = *(const float2*)&c.A[(size_t)(row0+am)*c.lda + kc + ak];
        }
        As[ak][am]=a2.x; As[ak+1][am]=a2.y;
        float4 b0 = make_float4(0.f,0.f,0.f,0.f), b1 = b0;
        if(bn<96){
            b0 = *(const float4*)&c.B[(size_t)(kc+bk)*96 + bn];
            b1 = *(const float4*)&c.B[(size_t)(kc+bk+8)*96 + bn];
        }
        *(float4*)&Bs[bk][bn]   = b0;
        *(float4*)&Bs[bk+8][bn] = b1;
        __syncthreads();
        #pragma unroll
        for(int k=0;k<16;k++){
            ULL av0 = *(const ULL*)&As[k][ty*4];
            ULL av1 = *(const ULL*)&As[k][ty*4+2];
            float4 bx = *(const float4*)&Bs[k][tx*4];
            ULL bd0=dup2(bx.x), bd1=dup2(bx.y), bd2=dup2(bx.z), bd3=dup2(bx.w);
            FFMA2(acc[0][0],av0,bd0); FFMA2(acc[0][1],av0,bd1);
            FFMA2(acc[0][2],av0,bd2); FFMA2(acc[0][3],av0,bd3);
            FFMA2(acc[1][0],av1,bd0); FFMA2(acc[1][1],av1,bd1);
            FFMA2(acc[1][2],av1,bd2); FFMA2(acc[1][3],av1,bd3);
        }
        __syncthreads();
    }
    int col = tx*4;
    if(col<96){
        #pragma unroll
        for(int rp=0;rp<2;rp++){
            int r = row0 + ty*4 + 2*rp;
            F2U t0,t1,t2,t3; t0.u=acc[rp][0]; t1.u=acc[rp][1]; t2.u=acc[rp][2]; t3.u=acc[rp][3];
            float vlo[4]={t0.f.x,t1.f.x,t2.f.x,t3.f.x};
            float vhi[4]={t0.f.y,t1.f.y,t2.f.y,t3.f.y};
            #pragma unroll
            for(int e=0;e<2;e++){
                int row = r+e;
                #pragma unroll
                for(int j=0;j<4;j++){
                    float v = (e? vhi[j] : vlo[j]) + c.bias[col+j];
                    if(c.epi==3) v = gelu_f(v);
                    if(c.epi==4){
                        v += addp[(size_t)row*96+col+j];
                        int b = row/21, d = row - b*21;
                        outp[(size_t)b*2016 + (col+j)*21 + d] = v;
                    } else {
                        c.C[(size_t)row*96+col+j] = v;
                    }
                }
            }
        }
    }
}

// ---- energy (warp per row) ----
__global__ void k_energy(){
    int gw = (blockIdx.x*256+threadIdx.x)>>5, lane = threadIdx.x&31;
    const float* z = g_zsplit + (size_t)gw*512;
    float s=0.f;
    for(int i=lane;i<512;i+=32){ float x=z[i]; s+=x*x; }
    for(int o=16;o;o>>=1) s += __shfl_xor_sync(~0u,s,o);
    if(lane==0) g_energy[gw]=s;
}

// ---- median over 21 per batch ----
__global__ void k_median(){
    int b = blockIdx.x, t = threadIdx.x;
    __shared__ float e[21]; __shared__ float med;
    if(t<21) e[t]=g_energy[b*21+t];
    __syncwarp();
    if(t<21){
        float x=e[t]; int less=0,eq=0;
        for(int j=0;j<21;j++){ float y=e[j]; less += (y<x); eq += (y==x); }
        if(less<=10 && 10<less+eq) med=x;
    }
    __syncwarp();
    if(t<21) g_norme[b*21+t] = e[t]/(med+1e-6f);
}

// ---- global quantile (radix select; 2 blocks, one per rank) ----
__global__ void k_quantile(const float* __restrict__ thr_p){
    __shared__ unsigned vals[5376];
    __shared__ unsigned hist[256];
    __shared__ unsigned s_pref; __shared__ int s_r;
    int tid = threadIdx.x;
    for(int i=tid;i<5376;i+=1024) vals[i]=__float_as_uint(g_norme[i]);
    float pos = thr_p[0]*5375.0f;
    int i0 = (int)floorf(pos);
    int r = blockIdx.x ? ((i0+1<5376)?i0+1:5375) : i0;
    unsigned prefix=0, msk=0;
    for(int shift=24;shift>=0;shift-=8){
        if(tid<256) hist[tid]=0;
        __syncthreads();
        for(int i=tid;i<5376;i+=1024){
            unsigned xv=vals[i];
            if((xv&msk)==prefix) atomicAdd(&hist[(xv>>shift)&255],1u);
        }
        __syncthreads();
        if(tid==0){
            unsigned acc=0;
            for(int bk=0;bk<256;bk++){
                unsigned nb=hist[bk];
                if(acc+nb>(unsigned)r){ s_pref=prefix|((unsigned)bk<<shift); s_r=r-(int)acc; break; }
                acc+=nb;
            }
        }
        __syncthreads();
        prefix=s_pref; r=s_r; msk|=(255u<<shift);
        __syncthreads();
    }
    if(tid==0) g_thr[blockIdx.x]=__uint_as_float(prefix);
}

// ---- mask + scale + gelu + CH stats ----
__global__ void k_maskgelu(const float* __restrict__ wdct, const float* __restrict__ bdct,
                           const float* __restrict__ thr_p){
    __shared__ float rs[2];
    int bd = blockIdx.x, tid = threadIdx.x;
    int d = bd - (bd/21)*21;
    float pos = thr_p[0]*5375.0f;
    float fr = pos - floorf(pos);
    float thr = g_thr[0] + fr*(g_thr[1]-g_thr[0]);
    float msk = (g_norme[bd] > thr) ? 1.f : 0.f;
    float wd = wdct[d]*msk, b0 = bdct[d];
    if(tid<2) rs[tid]=0.f;
    __syncthreads();
    float ls=0.f, lq=0.f;
    #pragma unroll
    for(int h=0;h<2;h++){
        size_t o=(size_t)bd*512 + tid + h*256;
        float g2 = gelu_f(g_zsplit[o]*wd + b0);
        g_zsplit[o]=g2; ls+=g2; lq+=g2*g2;
    }
    #pragma unroll
    for(int o=16;o;o>>=1){ ls += __shfl_xor_sync(~0u,ls,o); lq += __shfl_xor_sync(~0u,lq,o); }
    if((tid&31)==0){ atomicAdd(&rs[0],ls); atomicAdd(&rs[1],lq); }
    __syncthreads();
    if(tid==0){ atomicAdd(&g_stats[CHB+d],rs[0]); atomicAdd(&g_stats[CHB+32+d],rs[1]); }
}

__global__ void k_finalize(int base, int nch, float invN,
                           const float* __restrict__ g, const float* __restrict__ b){
    int c = threadIdx.x; if(c>=nch) return;
    float s = g_stats[base+c], sq = g_stats[base+32+c];
    float m = s*invN, v = sq*invN - m*m;
    float a = g[c]*rsqrtf(v+1e-5f);
    g_stats[base+64+c]=a; g_stats[base+96+c]=b[c]-m*a;
}

// ---- fused: recombine inverse-DCT + BN fold + residual, then patch branch + PN stats ----
__global__ __launch_bounds__(256) void k_recpatch(const float* __restrict__ wdct,
                                                  const float* __restrict__ bdct){
    __shared__ float xr[512]; __shared__ float ps[32], pq[32];
    int bd = blockIdx.x, tid = threadIdx.x;
    int d = bd - (bd/21)*21;
    size_t r5 = (size_t)bd*512;
    xr[tid]     = g_xt[r5+tid];
    xr[tid+256] = g_xt[r5+tid+256];
    if(tid<32){ ps[tid]=0.f; pq[tid]=0.f; }
    __syncthreads();
    {
        float a = g_stats[CHB+64+d], c = g_stats[CHB+96+d];
        float wd = wdct[d], b0 = bdct[d];
        size_t r2 = (size_t)bd*256+tid;
        float u = g_u[r2], v = g_v[r2];
        g_z1[r5+tid]     = a*(u+v) + c*(g_ce[tid]+g_co[tid]) + xr[tid]*wd + b0;
        g_z1[r5+511-tid] = a*(u-v) + c*(g_ce[tid]-g_co[tid]) + xr[511-tid]*wd + b0;
    }
    #pragma unroll
    for(int h=0;h<2;h++){
        int c2 = tid + h*256, n = c2>>4, q = c2&15;
        float s = g_bias2[c2];
        const float* Mr = &g_Mpatch[n*256+q*16];
        const float* xp = &xr[n*16];
        #pragma unroll
        for(int i=0;i<16;i++) s += xp[i]*Mr[i];
        g_s1[r5+c2]=s;
        float sq = s*s;
        #pragma unroll
        for(int o=8;o;o>>=1){ s += __shfl_xor_sync(~0u,s,o); sq += __shfl_xor_sync(~0u,sq,o); }
        if((tid&15)==0){ atomicAdd(&ps[n],s); atomicAdd(&pq[n],sq); }
    }
    __syncthreads();
    if(tid<32){ atomicAdd(&g_stats[PNB+tid],ps[tid]); atomicAdd(&g_stats[PNB+32+tid],pq[tid]); }
}

// ---- z2 = gelu(bn(s1)); zc_pre = conv3(z2); DN stats ----
__global__ void k_conv(const float* __restrict__ wdc1, const float* __restrict__ bdc1){
    __shared__ float z2s[512]; __shared__ float ss[32], sq2[32];
    int bd = blockIdx.x, tid = threadIdx.x;
    size_t r5 = (size_t)bd*512;
    if(tid<32){ ss[tid]=0.f; sq2[tid]=0.f; }
    #pragma unroll
    for(int h=0;h<2;h++){
        int c = tid + h*256, n = c>>4;
        float a = g_stats[PNB+64+n], cc = g_stats[PNB+96+n];
        float g2 = gelu_f(g_s1[r5+c]*a + cc);
        z2s[c]=g2; g_z2[r5+c]=g2;
    }
    __syncthreads();
    #pragma unroll
    for(int h=0;h<2;h++){
        int c = tid + h*256, n = c>>4, q = c&15;
        float l = q>0 ? z2s[c-1] : 0.f;
        float m0 = z2s[c];
        float r = q<15 ? z2s[c+1] : 0.f;
        float zc = wdc1[n*3+0]*l + wdc1[n*3+1]*m0 + wdc1[n*3+2]*r + bdc1[n];
        g_zcp[r5+c]=zc;
        float s=zc, sq=zc*zc;
        #pragma unroll
        for(int o=8;o;o>>=1){ s += __shfl_xor_sync(~0u,s,o); sq += __shfl_xor_sync(~0u,sq,o); }
        if((tid&15)==0){ atomicAdd(&ss[n],s); atomicAdd(&sq2[n],sq); }
    }
    __syncthreads();
    if(tid<32){ atomicAdd(&g_stats[DNB+tid],ss[tid]); atomicAdd(&g_stats[DNB+32+tid],sq2[tid]); }
}

// ---- fused: z2f = gelu(bn(zcp)) + z2 (into g_z2), attention dot + stats ----
__global__ void k_z2att(const float* __restrict__ adwb){
    __shared__ float red[8];
    int bd = blockIdx.x, tid = threadIdx.x;
    size_t r5 = (size_t)bd*512;
    float dot = 0.f;
    #pragma unroll
    for(int h=0;h<2;h++){
        int c = tid + h*256, n = c>>4;
        float a = g_stats[DNB+64+n], cc = g_stats[DNB+96+n];
        float z2f = gelu_f(g_zcp[r5+c]*a + cc) + g_z2[r5+c];
        g_z2[r5+c] = z2f;
        dot += g_z1[r5+c]*z2f*g_attcoef[c];
    }
    #pragma unroll
    for(int o=16;o;o>>=1) dot += __shfl_xor_sync(~0u,dot,o);
    if((tid&31)==0) red[tid>>5]=dot;
    __syncthreads();
    if(tid<8){
        float s = red[tid];
        #pragma unroll
        for(int o=4;o;o>>=1) s += __shfl_xor_sync(0xffu,s,o);
        if(tid==0){
            float att = s + adwb[0];
            g_att[bd]=att;
            atomicAdd(&g_stats[ATT_SUM],att);
            atomicAdd(&g_stats[ATT_SQ],att*att);
        }
    }
}

// ---- BN(att) + gelu + softmax over 21 ----
__global__ void k_softmax(const float* __restrict__ ag, const float* __restrict__ ab,
                          const float* __restrict__ cw, const float* __restrict__ cb){
    int b = blockIdx.x, t = threadIdx.x;
    float inv = 1.0f/5376.0f;
    float m = g_stats[ATT_SUM]*inv;
    float v = g_stats[ATT_SQ]*inv - m*m;
    float val = -1e30f;
    if(t<21){
        float a = g_att[b*21+t];
        a = ag[0]*(a-m)*rsqrtf(v+1e-5f)+ab[0];
        a = gelu_f(a);
        val = a*cw[0]+cb[0];
    }
    float mx = val;
    for(int o=16;o;o>>=1) mx = fmaxf(mx,__shfl_xor_sync(~0u,mx,o));
    float e = (t<21) ? expf(val-mx) : 0.f;
    float sum = e;
    for(int o=16;o;o>>=1) sum += __shfl_xor_sync(~0u,sum,o);
    if(t<21) g_att1[b*21+t] = e/sum;
}

extern "C" void kernel_launch(void* const* d_in, const int* in_sizes, int n_in,
                              void* d_out, int out_size){
    const float* x        =(const float*)d_in[0];
    const float* w_dct    =(const float*)d_in[1];
    const float* b_dct    =(const float*)d_in[2];
    const float* W_embed  =(const float*)d_in[3];
    const float* b_embed  =(const float*)d_in[4];
    const float* W_linres =(const float*)d_in[5];
    const float* b_linres =(const float*)d_in[6];
    const float* W_dres   =(const float*)d_in[7];
    const float* b_dres   =(const float*)d_in[8];
    const float* w_dc     =(const float*)d_in[9];
    const float* b_dc     =(const float*)d_in[10];
    const float* w_dc1    =(const float*)d_in[11];
    const float* b_dc1    =(const float*)d_in[12];
    const float* g_dctn   =(const float*)d_in[13];
    const float* b_dctn   =(const float*)d_in[14];
    const float* g_patn   =(const float*)d_in[15];
    const float* b_patn   =(const float*)d_in[16];
    const float* g_depn   =(const float*)d_in[17];
    const float* b_depn   =(const float*)d_in[18];
    const float* thr_p    =(const float*)d_in[19];
    const float* W_m1     =(const float*)d_in[20];
    const float* b_m1     =(const float*)d_in[21];
    const float* W_m2     =(const float*)d_in[22];
    const float* b_m2     =(const float*)d_in[23];
    const float* a_dw_w   =(const float*)d_in[24];
    const float* a_dw_b   =(const float*)d_in[25];
    const float* a_cw     =(const float*)d_in[26];
    const float* a_cb     =(const float*)d_in[27];
    const float* a_g      =(const float*)d_in[28];
    const float* a_b      =(const float*)d_in[29];
    float* out = (float*)d_out;

    float *p_xs,*p_xd,*p_BE,*p_BO,*p_BPe,*p_BPo,*p_zs,*p_u,*p_v,*p_xt,*p_Wf,*p_bL,*p_zr,*p_h;
    cudaGetSymbolAddress((void**)&p_xs,  g_xs);
    cudaGetSymbolAddress((void**)&p_xd,  g_xd);
    cudaGetSymbolAddress((void**)&p_BE,  g_BE);
    cudaGetSymbolAddress((void**)&p_BO,  g_BO);
    cudaGetSymbolAddress((void**)&p_BPe, g_BPe);
    cudaGetSymbolAddress((void**)&p_BPo, g_BPo);
    cudaGetSymbolAddress((void**)&p_zs,  g_zsplit);
    cudaGetSymbolAddress((void**)&p_u,   g_u);
    cudaGetSymbolAddress((void**)&p_v,   g_v);
    cudaGetSymbolAddress((void**)&p_xt,  g_xt);
    cudaGetSymbolAddress((void**)&p_Wf,  g_Wfold);
    cudaGetSymbolAddress((void**)&p_bL,  g_biasL);
    cudaGetSymbolAddress((void**)&p_zr,  g_zres);
    cudaGetSymbolAddress((void**)&p_h,   g_h);

    k_mats<<<257,256>>>(a_dw_w);
    k_fold1<<<192,256>>>(W_embed,W_linres,b_linres);
    k_fold2<<<48,256>>>(W_embed,b_embed,W_linres,W_dres,b_dres,w_dc,b_dc);
    k_transpose<<<dim3(256,2),256>>>(x);

    // forward DCT pair (even/odd)
    k_gemmA<<<dim3(84,2,2),256>>>(p_xs,p_xd,256, p_BE,p_BO, p_zs,p_zs+256,512);
    k_energy<<<672,256>>>();
    k_median<<<256,32>>>();
    k_quantile<<<2,1024>>>(thr_p);
    k_maskgelu<<<BD,256>>>(w_dct,b_dct,thr_p);
    k_finalize<<<1,32>>>(CHB,21,1.0f/131072.0f,g_dctn,b_dctn);
    // inverse DCT pair
    k_gemmA<<<dim3(84,2,2),256>>>(p_zs,p_zs+256,512, p_BPe,p_BPo, p_u,p_v,256);
    k_recpatch<<<BD,256>>>(w_dct,b_dct);
    k_finalize<<<1,32>>>(PNB,32,1.0f/86016.0f,g_patn,b_patn);
    k_conv<<<BD,256>>>(w_dc1,b_dc1);
    k_finalize<<<1,32>>>(DNB,32,1.0f/86016.0f,g_depn,b_depn);
    k_z2att<<<BD,256>>>(a_dw_b);
    k_softmax<<<256,32>>>(a_g,a_b,a_cw,a_cb);
    // output GEMMs: z=0 -> zres = xt@Wfold+biasL ; z=1 -> h = gelu(zsum@W_m1+b_m1)
    Cfg cW; cW.A=p_xt; cW.B=p_Wf;  cW.C=p_zr; cW.bias=p_bL; cW.lda=512; cW.K=512; cW.epi=2; cW.az=0;
    Cfg cM1; cM1.A=nullptr; cM1.B=W_m1; cM1.C=p_h; cM1.bias=b_m1; cM1.lda=512; cM1.K=512; cM1.epi=3; cM1.az=1;
    k_gemmB<<<dim3(168,1,2),256>>>(cW,cM1,nullptr,nullptr);
    Cfg cM2; cM2.A=p_h; cM2.B=W_m2; cM2.C=nullptr; cM2.bias=b_m2; cM2.lda=96; cM2.K=96; cM2.epi=4; cM2.az=0;
    k_gemmB<<<dim3(168,1,1),256>>>(cM2,cM2,p_zr,out);
}

// round 5
// speedup vs baseline: 1.6963x; 1.1361x over previous
#include <cuda_runtime.h>
#include <cuda_bf16.h>

#define BD 5376
#define CHB 0
#define PNB 128
#define DNB 256
#define ATT_SUM 384
#define ATT_SQ 385
#define PIF 3.14159265358979323846f

typedef unsigned long long ULL;
union F2U { ULL u; float2 f; };

__device__ float g_BE[65536], g_BO[65536], g_BPe[65536], g_BPo[65536];
__device__ float g_ce[256], g_co[256], g_attcoef[512];
__device__ float g_Wfold[49152], g_biasL[96], g_Mpatch[8192], g_bias2[512];
__device__ float g_xt[BD*512], g_xs[BD*256], g_xd[BD*256];
__device__ float g_zsplit[BD*512], g_u[BD*256], g_v[BD*256], g_z1[BD*512];
__device__ float g_s1[BD*512], g_z2[BD*512];
__device__ float g_zres[BD*96], g_h[BD*96];
__device__ float g_energy[BD], g_norme[BD], g_att[BD], g_att1[BD];
__device__ float g_thr[2], g_stats[512];

__device__ __forceinline__ float gelu_f(float x){
    return 0.5f*x*(1.0f+erff(x*0.70710678118654752440f));
}
__device__ __forceinline__ ULL dup2(float x){ ULL r; asm("mov.b64 %0,{%1,%1};":"=l"(r):"f"(x)); return r; }
#define FFMA2(d,a,b) asm("fma.rn.f32x2 %0, %1, %2, %0;" : "+l"(d) : "l"(a), "l"(b))

// ---- DCT matrices + attcoef + stats zero ----
__global__ void k_mats(const float* __restrict__ adw){
    int bm = blockIdx.x, t = threadIdx.x;
    if(bm < 256){
        int m = bm, j = t;
        float am = PIF*(float)(2*m+1);
        float ce = cosf(am*(float)(2*j)*(1.0f/1024.0f));
        float co = cosf(am*(float)(2*j+1)*(1.0f/1024.0f));
        g_BE[m*256+j] = 2.0f*ce;
        g_BO[m*256+j] = 2.0f*co;
        float bpe = ce*((j==0)?0.5f:1.0f)*(1.0f/512.0f);
        float bpo = co*(1.0f/512.0f);
        g_BPe[j*256+m] = bpe;
        g_BPo[j*256+m] = bpo;
        __shared__ float r1[256], r2[256];
        r1[t]=bpe; r2[t]=bpo; __syncthreads();
        for(int o=128;o>0;o>>=1){ if(t<o){ r1[t]+=r1[t+o]; r2[t]+=r2[t+o]; } __syncthreads(); }
        if(t==0){ g_ce[m]=r1[0]; g_co[m]=r2[0]; }
    } else {
        float rL = sqrtf(512.0f);
        for(int m=t; m<512; m+=256){
            float am = PIF*(float)(2*m+1);
            float s = 0.f;
            for(int k=0;k<5;k++){
                float c = 2.0f*cosf(am*(float)k*(1.0f/1024.0f));
                float so = (k==0)? (0.5f/rL) : (0.5f*sqrtf(2.0f)/rL);
                s += adw[k]*so*c;
            }
            g_attcoef[m]=s;
        }
        g_stats[t]=0.f; g_stats[t+256]=0.f;
    }
}

// ---- weight folding ----
__global__ void k_fold1(const float* __restrict__ We, const float* __restrict__ Wl,
                        const float* __restrict__ bl){
    int id = blockIdx.x*256+threadIdx.x;
    if(id<96) g_biasL[id]=bl[id];
    if(id>=49152) return;
    int c=id/96, t=id%96, n=c>>4, p=c&15;
    float s=0.f;
    for(int j=0;j<256;j++) s += We[p*256+j]*Wl[(n*256+j)*96+t];
    g_Wfold[id]=s;
}

__global__ void k_fold2(const float* __restrict__ We, const float* __restrict__ be,
                        const float* __restrict__ Wl, const float* __restrict__ Wd,
                        const float* __restrict__ bdres, const float* __restrict__ wdc,
                        const float* __restrict__ bdc){
    int id = blockIdx.x*256+threadIdx.x;
    if(id<8192){
        int n=id/256, q=(id>>4)&15, i=id&15;
        float s=0.f;
        #pragma unroll
        for(int p=0;p<16;p++) s += We[i*256+q*16+p]*wdc[n*16+p];
        for(int j=0;j<256;j++) s += We[i*256+j]*Wd[j*16+q];
        g_Mpatch[id]=s;
    } else if(id<8704){
        int c=id-8192, n=c>>4, q=c&15;
        float s = bdc[n]+bdres[q];
        #pragma unroll
        for(int p=0;p<16;p++) s += be[q*16+p]*wdc[n*16+p];
        for(int j=0;j<256;j++) s += be[j]*Wd[j*16+q];
        g_bias2[c]=s;
    } else if(id<11776){
        int q=id-8704, n=q/96, t=q%96;
        float s=0.f;
        for(int j=0;j<256;j++) s += be[j]*Wl[(n*256+j)*96+t];
        atomicAdd(&g_biasL[t], s);
    }
}

// ---- transpose + symmetric split ----
__global__ __launch_bounds__(256) void k_transpose(const float* __restrict__ x){
    __shared__ float sa[128*21], sb[128*21];
    int b = blockIdx.x, c = blockIdx.y, tid = threadIdx.x;
    int l0 = c*128, l1 = (3-c)*128;
    const float* xb = x + (size_t)b*512*21;
    for(int i=tid;i<128*21;i+=256){ sa[i]=xb[l0*21+i]; sb[i]=xb[l1*21+i]; }
    __syncthreads();
    int t = tid&127;
    for(int d=(tid>>7); d<21; d+=2){
        size_t row = (size_t)(b*21+d);
        float va = sa[t*21+d], vb = sb[(127-t)*21+d], vb2 = sb[t*21+d];
        g_xt[row*512+l0+t]=va;
        g_xt[row*512+l1+t]=vb2;
        g_xs[row*256+l0+t]=va+vb;
        g_xd[row*256+l0+t]=va-vb;
    }
}

// ---- DCT GEMM: M64 x N128, K=256, 256 thr, 8 rows x 4 cols/thread ----
__global__ __launch_bounds__(256,3) void k_gemmA(
    const float* __restrict__ A0, const float* __restrict__ A1, int lda,
    const float* __restrict__ B0, const float* __restrict__ B1,
    float* __restrict__ C0, float* __restrict__ C1, int ldc)
{
    const float* A  = blockIdx.z ? A1 : A0;
    const float* Bm = blockIdx.z ? B1 : B0;
    float* C        = blockIdx.z ? C1 : C0;
    __shared__ float As[16][66];
    __shared__ __align__(16) float Bs[16][128];
    int row0 = blockIdx.x*64, col0 = blockIdx.y*128;
    int tid = threadIdx.x, tx = tid&31, ty = tid>>5;
    int am = tid&63, ak = (tid>>6)*4;
    int bn = (tid&31)*4, bk = tid>>5;
    ULL acc[4][4] = {};
    for(int kc=0;kc<256;kc+=16){
        float4 a4 = *(const float4*)&A[(size_t)(row0+am)*lda + kc + ak];
        As[ak+0][am]=a4.x; As[ak+1][am]=a4.y; As[ak+2][am]=a4.z; As[ak+3][am]=a4.w;
        float4 b0 = *(const float4*)&Bm[(size_t)(kc+bk)*256 + col0 + bn];
        float4 b1 = *(const float4*)&Bm[(size_t)(kc+bk+8)*256 + col0 + bn];
        *(float4*)&Bs[bk][bn]   = b0;
        *(float4*)&Bs[bk+8][bn] = b1;
        __syncthreads();
        #pragma unroll
        for(int k=0;k<16;k++){
            ULL av[4];
            #pragma unroll
            for(int rp=0;rp<4;rp++) av[rp] = *(const ULL*)&As[k][ty*8+2*rp];
            float4 bx = *(const float4*)&Bs[k][tx*4];
            ULL bd0=dup2(bx.x), bd1=dup2(bx.y), bd2=dup2(bx.z), bd3=dup2(bx.w);
            #pragma unroll
            for(int rp=0;rp<4;rp++){
                FFMA2(acc[rp][0],av[rp],bd0);
                FFMA2(acc[rp][1],av[rp],bd1);
                FFMA2(acc[rp][2],av[rp],bd2);
                FFMA2(acc[rp][3],av[rp],bd3);
            }
        }
        __syncthreads();
    }
    int col = col0 + tx*4;
    #pragma unroll
    for(int rp=0;rp<4;rp++){
        int r = row0 + ty*8 + 2*rp;
        F2U t0,t1,t2,t3; t0.u=acc[rp][0]; t1.u=acc[rp][1]; t2.u=acc[rp][2]; t3.u=acc[rp][3];
        float4 lo = make_float4(t0.f.x,t1.f.x,t2.f.x,t3.f.x);
        float4 hi = make_float4(t0.f.y,t1.f.y,t2.f.y,t3.f.y);
        *(float4*)&C[(size_t)r*ldc + col]     = lo;
        *(float4*)&C[(size_t)(r+1)*ldc + col] = hi;
    }
}

// ---- Output GEMM: M32 x N96(padded 128) ----
struct Cfg { const float* A; const float* B; float* C; const float* bias;
             int lda; int K; int epi; int az; };

__global__ __launch_bounds__(256,4) void k_gemmB(Cfg c0,
        const float* __restrict__ addp, float* __restrict__ outp)
{
    Cfg c = c0;
    __shared__ float As[16][34];
    __shared__ __align__(16) float Bs[16][128];
    int row0 = blockIdx.x*32;
    int tid = threadIdx.x, tx = tid&31, ty = tid>>5;
    int am = tid&31, ak = (tid>>5)*2;
    int bn = (tid&31)*4, bk = tid>>5;
    ULL acc[2][4] = {};
    float w = 0.f;
    if(c.az) w = g_att1[row0+am];
    for(int kc=0;kc<c.K;kc+=16){
        float2 a2;
        if(c.az){
            size_t o = (size_t)(row0+am)*512 + kc + ak;
            float2 z1v = *(const float2*)&g_z1[o];
            float2 z2v = *(const float2*)&g_z2[o];
            a2.x = z1v.x*w + z2v.x*(1.0f-w);
            a2.y = z1v.y*w + z2v.y*(1.0f-w);
        } else {
            a2 = *(const float2*)&c.A[(size_t)(row0+am)*c.lda + kc + ak];
        }
        As[ak][am]=a2.x; As[ak+1][am]=a2.y;
        float4 b0 = make_float4(0.f,0.f,0.f,0.f), b1 = b0;
        if(bn<96){
            b0 = *(const float4*)&c.B[(size_t)(kc+bk)*96 + bn];
            b1 = *(const float4*)&c.B[(size_t)(kc+bk+8)*96 + bn];
        }
        *(float4*)&Bs[bk][bn]   = b0;
        *(float4*)&Bs[bk+8][bn] = b1;
        __syncthreads();
        #pragma unroll
        for(int k=0;k<16;k++){
            ULL av0 = *(const ULL*)&As[k][ty*4];
            ULL av1 = *(const ULL*)&As[k][ty*4+2];
            float4 bx = *(const float4*)&Bs[k][tx*4];
            ULL bd0=dup2(bx.x), bd1=dup2(bx.y), bd2=dup2(bx.z), bd3=dup2(bx.w);
            FFMA2(acc[0][0],av0,bd0); FFMA2(acc[0][1],av0,bd1);
            FFMA2(acc[0][2],av0,bd2); FFMA2(acc[0][3],av0,bd3);
            FFMA2(acc[1][0],av1,bd0); FFMA2(acc[1][1],av1,bd1);
            FFMA2(acc[1][2],av1,bd2); FFMA2(acc[1][3],av1,bd3);
        }
        __syncthreads();
    }
    int col = tx*4;
    if(col<96){
        #pragma unroll
        for(int rp=0;rp<2;rp++){
            int r = row0 + ty*4 + 2*rp;
            F2U t0,t1,t2,t3; t0.u=acc[rp][0]; t1.u=acc[rp][1]; t2.u=acc[rp][2]; t3.u=acc[rp][3];
            float vlo[4]={t0.f.x,t1.f.x,t2.f.x,t3.f.x};
            float vhi[4]={t0.f.y,t1.f.y,t2.f.y,t3.f.y};
            #pragma unroll
            for(int e=0;e<2;e++){
                int row = r+e;
                #pragma unroll
                for(int j=0;j<4;j++){
                    float v = (e? vhi[j] : vlo[j]) + c.bias[col+j];
                    if(c.epi==3) v = gelu_f(v);
                    if(c.epi==4){
                        v += addp[(size_t)row*96+col+j];
                        int b = row/21, d = row - b*21;
                        outp[(size_t)b*2016 + (col+j)*21 + d] = v;
                    } else {
                        c.C[(size_t)row*96+col+j] = v;
                    }
                }
            }
        }
    }
}

// ---- energy (warp per row) ----
__global__ void k_energy(){
    int gw = (blockIdx.x*256+threadIdx.x)>>5, lane = threadIdx.x&31;
    const float* z = g_zsplit + (size_t)gw*512;
    float s=0.f;
    for(int i=lane;i<512;i+=32){ float x=z[i]; s+=x*x; }
    for(int o=16;o;o>>=1) s += __shfl_xor_sync(~0u,s,o);
    if(lane==0) g_energy[gw]=s;
}

// ---- fused median (per-batch over 21) + global quantile radix select; 2 blocks ----
__global__ __launch_bounds__(1024) void k_medquant(const float* __restrict__ thr_p){
    __shared__ float e[5376]; __shared__ float med[256];
    __shared__ unsigned vals[5376];
    __shared__ unsigned hist[256];
    __shared__ unsigned s_pref; __shared__ int s_r;
    int tid = threadIdx.x;
    for(int i=tid;i<5376;i+=1024) e[i]=g_energy[i];
    __syncthreads();
    if(tid<256){
        int b0 = tid*21;
        float m=0.f;
        for(int j=0;j<21;j++){
            float xj=e[b0+j]; int less=0,eq=0;
            for(int k2=0;k2<21;k2++){ float y=e[b0+k2]; less+=(y<xj); eq+=(y==xj); }
            if(less<=10 && 10<less+eq) m=xj;
        }
        med[tid]=m;
    }
    __syncthreads();
    for(int i=tid;i<5376;i+=1024){
        float nm = e[i]/(med[i/21]+1e-6f);
        vals[i]=__float_as_uint(nm);
        if(blockIdx.x==0) g_norme[i]=nm;
    }
    float pos = thr_p[0]*5375.0f;
    int i0 = (int)floorf(pos);
    int r = blockIdx.x ? ((i0+1<5376)?i0+1:5375) : i0;
    unsigned prefix=0, msk=0;
    for(int shift=24;shift>=0;shift-=8){
        if(tid<256) hist[tid]=0;
        __syncthreads();
        for(int i=tid;i<5376;i+=1024){
            unsigned xv=vals[i];
            if((xv&msk)==prefix) atomicAdd(&hist[(xv>>shift)&255],1u);
        }
        __syncthreads();
        if(tid==0){
            unsigned acc=0;
            for(int bk=0;bk<256;bk++){
                unsigned nb=hist[bk];
                if(acc+nb>(unsigned)r){ s_pref=prefix|((unsigned)bk<<shift); s_r=r-(int)acc; break; }
                acc+=nb;
            }
        }
        __syncthreads();
        prefix=s_pref; r=s_r; msk|=(255u<<shift);
        __syncthreads();
    }
    if(tid==0) g_thr[blockIdx.x]=__uint_as_float(prefix);
}

// ---- mask + scale + gelu + CH stats ----
__global__ void k_maskgelu(const float* __restrict__ wdct, const float* __restrict__ bdct,
                           const float* __restrict__ thr_p){
    __shared__ float rs[2];
    int bd = blockIdx.x, tid = threadIdx.x;
    int d = bd - (bd/21)*21;
    float pos = thr_p[0]*5375.0f;
    float fr = pos - floorf(pos);
    float thr = g_thr[0] + fr*(g_thr[1]-g_thr[0]);
    float msk = (g_norme[bd] > thr) ? 1.f : 0.f;
    float wd = wdct[d]*msk, b0 = bdct[d];
    if(tid<2) rs[tid]=0.f;
    __syncthreads();
    float ls=0.f, lq=0.f;
    #pragma unroll
    for(int h=0;h<2;h++){
        size_t o=(size_t)bd*512 + tid + h*256;
        float g2 = gelu_f(g_zsplit[o]*wd + b0);
        g_zsplit[o]=g2; ls+=g2; lq+=g2*g2;
    }
    #pragma unroll
    for(int o=16;o;o>>=1){ ls += __shfl_xor_sync(~0u,ls,o); lq += __shfl_xor_sync(~0u,lq,o); }
    if((tid&31)==0){ atomicAdd(&rs[0],ls); atomicAdd(&rs[1],lq); }
    __syncthreads();
    if(tid==0){ atomicAdd(&g_stats[CHB+d],rs[0]); atomicAdd(&g_stats[CHB+32+d],rs[1]); }
}

__global__ void k_finalize(int base, int nch, float invN,
                           const float* __restrict__ g, const float* __restrict__ b){
    int c = threadIdx.x; if(c>=nch) return;
    float s = g_stats[base+c], sq = g_stats[base+32+c];
    float m = s*invN, v = sq*invN - m*m;
    float a = g[c]*rsqrtf(v+1e-5f);
    g_stats[base+64+c]=a; g_stats[base+96+c]=b[c]-m*a;
}

// ---- recombine inverse-DCT + BN fold + residual ----
__global__ __launch_bounds__(256) void k_recombine(const float* __restrict__ wdct,
                                                   const float* __restrict__ bdct){
    int bd = blockIdx.x, m = threadIdx.x;
    int d = bd - (bd/21)*21;
    float a = g_stats[CHB+64+d], c = g_stats[CHB+96+d];
    float wd = wdct[d], b0 = bdct[d];
    size_t r2 = (size_t)bd*256+m, r5 = (size_t)bd*512;
    float u = g_u[r2], v = g_v[r2];
    float x0 = g_xt[r5+m], x1 = g_xt[r5+511-m];
    g_z1[r5+m]     = a*(u+v) + c*(g_ce[m]+g_co[m]) + x0*wd + b0;
    g_z1[r5+511-m] = a*(u-v) + c*(g_ce[m]-g_co[m]) + x1*wd + b0;
}

// ---- patch branch: s1 + PN stats ----
__global__ __launch_bounds__(256) void k_patch(){
    __shared__ float xr[512]; __shared__ float ps[32], pq[32];
    int bd = blockIdx.x, tid = threadIdx.x;
    size_t r5 = (size_t)bd*512;
    xr[tid]     = g_xt[r5+tid];
    xr[tid+256] = g_xt[r5+tid+256];
    if(tid<32){ ps[tid]=0.f; pq[tid]=0.f; }
    __syncthreads();
    #pragma unroll
    for(int h=0;h<2;h++){
        int c2 = tid + h*256, n = c2>>4, q = c2&15;
        float s = g_bias2[c2];
        const float* Mr = &g_Mpatch[n*256+q*16];
        const float* xp = &xr[n*16];
        #pragma unroll
        for(int i=0;i<16;i++) s += xp[i]*Mr[i];
        g_s1[r5+c2]=s;
        float sq = s*s;
        #pragma unroll
        for(int o=8;o;o>>=1){ s += __shfl_xor_sync(~0u,s,o); sq += __shfl_xor_sync(~0u,sq,o); }
        if((tid&15)==0){ atomicAdd(&ps[n],s); atomicAdd(&pq[n],sq); }
    }
    __syncthreads();
    if(tid<32){ atomicAdd(&g_stats[PNB+tid],ps[tid]); atomicAdd(&g_stats[PNB+32+tid],pq[tid]); }
}

// ---- z2 = gelu(bn(s1)); DN stats of conv3(z2) (no zcp store) ----
__global__ void k_conv(const float* __restrict__ wdc1, const float* __restrict__ bdc1){
    __shared__ float z2s[512]; __shared__ float ss[32], sq2[32];
    int bd = blockIdx.x, tid = threadIdx.x;
    size_t r5 = (size_t)bd*512;
    if(tid<32){ ss[tid]=0.f; sq2[tid]=0.f; }
    #pragma unroll
    for(int h=0;h<2;h++){
        int c = tid + h*256, n = c>>4;
        float a = g_stats[PNB+64+n], cc = g_stats[PNB+96+n];
        float g2 = gelu_f(g_s1[r5+c]*a + cc);
        z2s[c]=g2; g_z2[r5+c]=g2;
    }
    __syncthreads();
    #pragma unroll
    for(int h=0;h<2;h++){
        int c = tid + h*256, n = c>>4, q = c&15;
        float l = q>0 ? z2s[c-1] : 0.f;
        float m0 = z2s[c];
        float r = q<15 ? z2s[c+1] : 0.f;
        float zc = wdc1[n*3+0]*l + wdc1[n*3+1]*m0 + wdc1[n*3+2]*r + bdc1[n];
        float s=zc, sq=zc*zc;
        #pragma unroll
        for(int o=8;o;o>>=1){ s += __shfl_xor_sync(~0u,s,o); sq += __shfl_xor_sync(~0u,sq,o); }
        if((tid&15)==0){ atomicAdd(&ss[n],s); atomicAdd(&sq2[n],sq); }
    }
    __syncthreads();
    if(tid<32){ atomicAdd(&g_stats[DNB+tid],ss[tid]); atomicAdd(&g_stats[DNB+32+tid],sq2[tid]); }
}

// ---- fused: recompute conv3(z2), z2f = gelu(bn(zc)) + z2 (into g_z2), attention dot ----
__global__ void k_z2att(const float* __restrict__ wdc1, const float* __restrict__ bdc1,
                        const float* __restrict__ adwb){
    __shared__ float z2s[512]; __shared__ float red[8];
    int bd = blockIdx.x, tid = threadIdx.x;
    size_t r5 = (size_t)bd*512;
    z2s[tid]     = g_z2[r5+tid];
    z2s[tid+256] = g_z2[r5+tid+256];
    __syncthreads();
    float dot = 0.f;
    #pragma unroll
    for(int h=0;h<2;h++){
        int c = tid + h*256, n = c>>4, q = c&15;
        float l = q>0 ? z2s[c-1] : 0.f;
        float m0 = z2s[c];
        float r = q<15 ? z2s[c+1] : 0.f;
        float zc = wdc1[n*3+0]*l + wdc1[n*3+1]*m0 + wdc1[n*3+2]*r + bdc1[n];
        float a = g_stats[DNB+64+n], cc = g_stats[DNB+96+n];
        float z2f = gelu_f(zc*a + cc) + m0;
        g_z2[r5+c] = z2f;
        dot += g_z1[r5+c]*z2f*g_attcoef[c];
    }
    #pragma unroll
    for(int o=16;o;o>>=1) dot += __shfl_xor_sync(~0u,dot,o);
    if((tid&31)==0) red[tid>>5]=dot;
    __syncthreads();
    if(tid<8){
        float s = red[tid];
        #pragma unroll
        for(int o=4;o;o>>=1) s += __shfl_xor_sync(0xffu,s,o);
        if(tid==0){
            float att = s + adwb[0];
            g_att[bd]=att;
            atomicAdd(&g_stats[ATT_SUM],att);
            atomicAdd(&g_stats[ATT_SQ],att*att);
        }
    }
}

// ---- BN(att) + gelu + softmax over 21 ----
__global__ void k_softmax(const float* __restrict__ ag, const float* __restrict__ ab,
                          const float* __restrict__ cw, const float* __restrict__ cb){
    int b = blockIdx.x, t = threadIdx.x;
    float inv = 1.0f/5376.0f;
    float m = g_stats[ATT_SUM]*inv;
    float v = g_stats[ATT_SQ]*inv - m*m;
    float val = -1e30f;
    if(t<21){
        float a = g_att[b*21+t];
        a = ag[0]*(a-m)*rsqrtf(v+1e-5f)+ab[0];
        a = gelu_f(a);
        val = a*cw[0]+cb[0];
    }
    float mx = val;
    for(int o=16;o;o>>=1) mx = fmaxf(mx,__shfl_xor_sync(~0u,mx,o));
    float e = (t<21) ? expf(val-mx) : 0.f;
    float sum = e;
    for(int o=16;o;o>>=1) sum += __shfl_xor_sync(~0u,sum,o);
    if(t<21) g_att1[b*21+t] = e/sum;
}

extern "C" void kernel_launch(void* const* d_in, const int* in_sizes, int n_in,
                              void* d_out, int out_size){
    const float* x        =(const float*)d_in[0];
    const float* w_dct    =(const float*)d_in[1];
    const float* b_dct    =(const float*)d_in[2];
    const float* W_embed  =(const float*)d_in[3];
    const float* b_embed  =(const float*)d_in[4];
    const float* W_linres =(const float*)d_in[5];
    const float* b_linres =(const float*)d_in[6];
    const float* W_dres   =(const float*)d_in[7];
    const float* b_dres   =(const float*)d_in[8];
    const float* w_dc     =(const float*)d_in[9];
    const float* b_dc     =(const float*)d_in[10];
    const float* w_dc1    =(const float*)d_in[11];
    const float* b_dc1    =(const float*)d_in[12];
    const float* g_dctn   =(const float*)d_in[13];
    const float* b_dctn   =(const float*)d_in[14];
    const float* g_patn   =(const float*)d_in[15];
    const float* b_patn   =(const float*)d_in[16];
    const float* g_depn   =(const float*)d_in[17];
    const float* b_depn   =(const float*)d_in[18];
    const float* thr_p    =(const float*)d_in[19];
    const float* W_m1     =(const float*)d_in[20];
    const float* b_m1     =(const float*)d_in[21];
    const float* W_m2     =(const float*)d_in[22];
    const float* b_m2     =(const float*)d_in[23];
    const float* a_dw_w   =(const float*)d_in[24];
    const float* a_dw_b   =(const float*)d_in[25];
    const float* a_cw     =(const float*)d_in[26];
    const float* a_cb     =(const float*)d_in[27];
    const float* a_g      =(const float*)d_in[28];
    const float* a_b      =(const float*)d_in[29];
    float* out = (float*)d_out;

    float *p_xs,*p_xd,*p_BE,*p_BO,*p_BPe,*p_BPo,*p_zs,*p_u,*p_v,*p_xt,*p_Wf,*p_bL,*p_zr,*p_h;
    cudaGetSymbolAddress((void**)&p_xs,  g_xs);
    cudaGetSymbolAddress((void**)&p_xd,  g_xd);
    cudaGetSymbolAddress((void**)&p_BE,  g_BE);
    cudaGetSymbolAddress((void**)&p_BO,  g_BO);
    cudaGetSymbolAddress((void**)&p_BPe, g_BPe);
    cudaGetSymbolAddress((void**)&p_BPo, g_BPo);
    cudaGetSymbolAddress((void**)&p_zs,  g_zsplit);
    cudaGetSymbolAddress((void**)&p_u,   g_u);
    cudaGetSymbolAddress((void**)&p_v,   g_v);
    cudaGetSymbolAddress((void**)&p_xt,  g_xt);
    cudaGetSymbolAddress((void**)&p_Wf,  g_Wfold);
    cudaGetSymbolAddress((void**)&p_bL,  g_biasL);
    cudaGetSymbolAddress((void**)&p_zr,  g_zres);
    cudaGetSymbolAddress((void**)&p_h,   g_h);

    // Fork-join: side stream handles weight folds + patch branch + zres GEMM.
    // Created per call (host-side cost only during capture, not replay); not
    // destroyed during active capture (destroying a capture-joined stream/event
    // would invalidate the capture).
    cudaStream_t s2;
    cudaStreamCreateWithFlags(&s2, cudaStreamNonBlocking);
    cudaEvent_t evA, evT, evJ;
    cudaEventCreateWithFlags(&evA, cudaEventDisableTiming);
    cudaEventCreateWithFlags(&evT, cudaEventDisableTiming);
    cudaEventCreateWithFlags(&evJ, cudaEventDisableTiming);

    cudaEventRecord(evA, 0);

    // main stream: DCT branch
    k_mats<<<257,256>>>(a_dw_w);
    k_transpose<<<dim3(256,2),256>>>(x);
    cudaEventRecord(evT, 0);

    // side stream: folds, patch branch, zres GEMM
    cudaStreamWaitEvent(s2, evA, 0);
    k_fold1<<<192,256,0,s2>>>(W_embed,W_linres,b_linres);
    k_fold2<<<46,256,0,s2>>>(W_embed,b_embed,W_linres,W_dres,b_dres,w_dc,b_dc);
    cudaStreamWaitEvent(s2, evT, 0);
    k_patch<<<BD,256,0,s2>>>();
    k_finalize<<<1,32,0,s2>>>(PNB,32,1.0f/86016.0f,g_patn,b_patn);
    k_conv<<<BD,256,0,s2>>>(w_dc1,b_dc1);
    k_finalize<<<1,32,0,s2>>>(DNB,32,1.0f/86016.0f,g_depn,b_depn);
    Cfg cW; cW.A=p_xt; cW.B=p_Wf; cW.C=p_zr; cW.bias=p_bL; cW.lda=512; cW.K=512; cW.epi=2; cW.az=0;
    k_gemmB<<<dim3(168,1,1),256,0,s2>>>(cW,nullptr,nullptr);
    cudaEventRecord(evJ, s2);

    // main stream continues: forward DCT, mask path, inverse DCT
    k_gemmA<<<dim3(84,2,2),256>>>(p_xs,p_xd,256, p_BE,p_BO, p_zs,p_zs+256,512);
    k_energy<<<672,256>>>();
    k_medquant<<<2,1024>>>(thr_p);
    k_maskgelu<<<BD,256>>>(w_dct,b_dct,thr_p);
    k_finalize<<<1,32>>>(CHB,21,1.0f/131072.0f,g_dctn,b_dctn);
    k_gemmA<<<dim3(84,2,2),256>>>(p_zs,p_zs+256,512, p_BPe,p_BPo, p_u,p_v,256);
    k_recombine<<<BD,256>>>(w_dct,b_dct);

    // join
    cudaStreamWaitEvent(0, evJ, 0);
    k_z2att<<<BD,256>>>(w_dc1,b_dc1,a_dw_b);
    k_softmax<<<256,32>>>(a_g,a_b,a_cw,a_cb);
    Cfg cM1; cM1.A=nullptr; cM1.B=W_m1; cM1.C=p_h; cM1.bias=b_m1; cM1.lda=512; cM1.K=512; cM1.epi=3; cM1.az=1;
    k_gemmB<<<dim3(168,1,1),256>>>(cM1,nullptr,nullptr);
    Cfg cM2; cM2.A=p_h; cM2.B=W_m2; cM2.C=nullptr; cM2.bias=b_m2; cM2.lda=96; cM2.K=96; cM2.epi=4; cM2.az=0;
    k_gemmB<<<dim3(168,1,1),256>>>(cM2,p_zr,out);
}